// round 12
// baseline (speedup 1.0000x reference)
#include <cuda_runtime.h>
#include <cuda_fp16.h>
#include <cstdint>
#include <math.h>

#define Bn   2
#define Tn   1024
#define Cn   1024
#define Hn   16
#define HSn  64
#define TTn  1024
#define FFNn 4096
#define EPSn 1e-6f

// ---------------- scratch ----------------
__device__ __half g_xs [Bn*Tn*Cn];
__device__ __half g_q  [Bn*Tn*Cn];
__device__ __half g_k  [Bn*Tn*Cn];
__device__ __half g_v  [Bn*Tn*Cn];          // k-pair packed per (b,h)
__device__ __half g_att [Bn*Hn*Tn*Tn];      // aliased as fp32 split-K partials
__device__ __half g_att2[Bn*Hn*Tn*Tn];
__device__ __half g_y  [Bn*Tn*Cn];
__device__ float  g_x1 [Bn*Tn*Cn];
__device__ __half g_xm [Bn*Tn*Cn];
__device__ __half g_gv [Bn*Tn*FFNn];
__device__ uint32_t g_wh[8*1024*1024];      // packed half2 weights, 32MB

#define WOFF_Q   0
#define WOFF_K   (512*1024)
#define WOFF_V   (2*512*1024)
#define WOFF_O   (3*512*1024)
#define WOFF_GK  (4*512*1024)
#define WOFF_GV  (WOFF_GK + 512*4096)
#define WOFF_GW  (WOFF_GV + 512*4096)

// ---------------- helpers ----------------
__device__ __forceinline__ void mma_fp16(float* d, const uint32_t* a, const uint32_t* b) {
    asm volatile(
        "mma.sync.aligned.m16n8k16.row.col.f32.f16.f16.f32 "
        "{%0,%1,%2,%3}, {%4,%5,%6,%7}, {%8,%9}, {%0,%1,%2,%3};"
        : "+f"(d[0]), "+f"(d[1]), "+f"(d[2]), "+f"(d[3])
        : "r"(a[0]), "r"(a[1]), "r"(a[2]), "r"(a[3]), "r"(b[0]), "r"(b[1]));
}
__device__ __forceinline__ uint32_t smem_u32(const void* p) {
    uint32_t a;
    asm("{ .reg .u64 t; cvta.to.shared.u64 t, %1; cvt.u32.u64 %0, t; }"
        : "=r"(a) : "l"(p));
    return a;
}
__device__ __forceinline__ void cp16(uint32_t dst, const void* src) {
    asm volatile("cp.async.ca.shared.global [%0], [%1], 16;" :: "r"(dst), "l"(src));
}
__device__ __forceinline__ void cp_commit() {
    asm volatile("cp.async.commit_group;" ::: "memory");
}
template<int N> __device__ __forceinline__ void cp_wait() {
    asm volatile("cp.async.wait_group %0;" :: "n"(N) : "memory");
}

// ---------------- weight conversion ----------------
struct W4 { const float* w[4]; };
__global__ void conv_cc(W4 ws) {
    int z = blockIdx.z;
    const float* W = ws.w[z];
    uint32_t* dst = g_wh + (size_t)z * (512*1024);
    int n  = blockIdx.x * 256 + threadIdx.x;
    int k2 = blockIdx.y;
    __half2 h = __floats2half2_rn(W[(size_t)(2*k2) * Cn + n],
                                  W[(size_t)(2*k2+1) * Cn + n]);
    dst[(size_t)k2 * Cn + n] = *(uint32_t*)&h;
}
__global__ void conv_cf(const float* W0, const float* W1) {
    int z = blockIdx.z;
    const float* W = z ? W1 : W0;
    uint32_t* dst = g_wh + WOFF_GK + (size_t)z * (512*4096);
    int n  = blockIdx.x * 256 + threadIdx.x;
    int k2 = blockIdx.y;
    __half2 h = __floats2half2_rn(W[(size_t)(2*k2) * FFNn + n],
                                  W[(size_t)(2*k2+1) * FFNn + n]);
    dst[(size_t)k2 * FFNn + n] = *(uint32_t*)&h;
}
__global__ void conv_fc(const float* W) {
    uint32_t* dst = g_wh + WOFF_GW;
    int n  = blockIdx.x * 256 + threadIdx.x;
    int k2 = blockIdx.y;
    __half2 h = __floats2half2_rn(W[(size_t)(2*k2) * Cn + n],
                                  W[(size_t)(2*k2+1) * Cn + n]);
    dst[(size_t)k2 * Cn + n] = *(uint32_t*)&h;
}

// ---------------- fast row reduce ----------------
__device__ __forceinline__ void row_stats(float4 v4, float& mean, float& rstd,
                                          float* red) {
    int tid = threadIdx.x, lane = tid & 31, w = tid >> 5;
    float s  = v4.x + v4.y + v4.z + v4.w;
    float s2 = v4.x*v4.x + v4.y*v4.y + v4.z*v4.z + v4.w*v4.w;
#pragma unroll
    for (int o = 16; o; o >>= 1) {
        s  += __shfl_xor_sync(0xFFFFFFFFu, s,  o);
        s2 += __shfl_xor_sync(0xFFFFFFFFu, s2, o);
    }
    if (lane == 0) { red[w] = s; red[8 + w] = s2; }
    __syncthreads();
    if (tid == 0) {
        float a = 0.f, b2 = 0.f;
#pragma unroll
        for (int i = 0; i < 8; i++) { a += red[i]; b2 += red[8 + i]; }
        red[16] = a; red[17] = b2;
    }
    __syncthreads();
    mean = red[16] / Cn;
    rstd = rsqrtf(red[17] / Cn - mean * mean + EPSn);
}

// ---------------- LN1 + time_shift_half ----------------
__global__ __launch_bounds__(256)
void ln1_shift_kernel(const float* __restrict__ x,
                      const float* __restrict__ g,
                      const float* __restrict__ b) {
    __shared__ float red[18];
    int bt = blockIdx.x;
    int bb = bt >> 10, t = bt & (Tn - 1);
    int c = threadIdx.x * 4;
    float4 v4 = *(const float4*)(x + (size_t)bt * Cn + c);
    float mean, rstd;
    row_stats(v4, mean, rstd, red);
    float4 g4 = *(const float4*)(g + c);
    float4 b4 = *(const float4*)(b + c);
    __half2 h01 = __floats2half2_rn((v4.x - mean) * rstd * g4.x + b4.x,
                                    (v4.y - mean) * rstd * g4.y + b4.y);
    __half2 h23 = __floats2half2_rn((v4.z - mean) * rstd * g4.z + b4.z,
                                    (v4.w - mean) * rstd * g4.w + b4.w);
    uint2 pk; pk.x = *(uint32_t*)&h01; pk.y = *(uint32_t*)&h23;
    if (c < Cn / 2) {
        if (t + 1 < Tn)
            *(uint2*)(g_xs + ((size_t)bb * Tn + t + 1) * Cn + c) = pk;
        if (t == 0)
            *(uint2*)(g_xs + (size_t)bb * Tn * Cn + c) = make_uint2(0, 0);
    } else {
        *(uint2*)(g_xs + (size_t)bt * Cn + c) = pk;
    }
}

// ---------------- fused fin_wo + LN2 ----------------
__global__ __launch_bounds__(256)
void ln2_fused(const float* __restrict__ P, const float* __restrict__ bo,
               const float* __restrict__ gamma, const float* __restrict__ x,
               const float* __restrict__ g, const float* __restrict__ b) {
    __shared__ float red[18];
    int bt = blockIdx.x;
    int t = bt & (Tn - 1);
    int c = threadIdx.x * 4;
    const size_t half = (size_t)(Bn * Tn) * Cn;
    size_t i = (size_t)bt * Cn + c;
    float4 a4 = *(const float4*)(P + i);
    float4 p4 = *(const float4*)(P + half + i);
    float4 x4 = *(const float4*)(x + i);
    float4 bo4 = *(const float4*)(bo + c);
    float gm = gamma[t];
    float4 v4;
    v4.x = (a4.x + p4.x + bo4.x) * gm + x4.x;
    v4.y = (a4.y + p4.y + bo4.y) * gm + x4.y;
    v4.z = (a4.z + p4.z + bo4.z) * gm + x4.z;
    v4.w = (a4.w + p4.w + bo4.w) * gm + x4.w;
    *(float4*)(g_x1 + i) = v4;
    float mean, rstd;
    row_stats(v4, mean, rstd, red);
    float4 g4 = *(const float4*)(g + c);
    float4 b4 = *(const float4*)(b + c);
    __half2 h01 = __floats2half2_rn((v4.x - mean) * rstd * g4.x + b4.x,
                                    (v4.y - mean) * rstd * g4.y + b4.y);
    __half2 h23 = __floats2half2_rn((v4.z - mean) * rstd * g4.z + b4.z,
                                    (v4.w - mean) * rstd * g4.w + b4.w);
    uint2 pk; pk.x = *(uint32_t*)&h01; pk.y = *(uint32_t*)&h23;
    *(uint2*)(g_xm + i) = pk;
}

// ============ fp16 GEMM core (128x128, 8 warps, K-chunk 64, 3-stage) ========
#define EPI_NONE  0
#define EPI_QKV   1

#define AW 36
#define BW 136
#define ABUFW (128*AW)             // 4608 words
#define BBUFW (32*BW)              // 4352 words
#define STGW  (ABUFW + BBUFW)      // 8960 words
#define GEMM_SMEMW (3*STGW)        // 26880 words = 107520 B

template<int MODE>
__device__ __forceinline__ void gemm_body(
    uint32_t* usm,
    const __half* __restrict__ A, const uint32_t* __restrict__ Bp,
    const float* __restrict__ bias, void* __restrict__ Cv,
    int N, int Kfull, int koff, int kspan,
    int row0, int col0, int qkvmode)
{
    uint32_t sb = smem_u32(usm);
    int tid = threadIdx.x;
    int lane = tid & 31, wid = tid >> 5;
    int wm = wid >> 2, wn = wid & 3;
    int lg = lane >> 2, lq = lane & 3;

    float acc[4][4][4] = {};

    int aw = (tid & 1) * 16;
    const __half* Ab = A + (size_t)(row0 + (tid >> 1)) * Kfull + koff + aw * 2;
    const uint32_t* Bb = Bp + ((size_t)(koff >> 1) + (tid >> 4)) * N + col0 + (tid & 15) * 8;
    uint32_t adst0 = sb + (uint32_t)(((tid >> 1) * AW + aw) * 4);
    uint32_t bdst0 = sb + (uint32_t)((ABUFW + (tid >> 4) * BW + (tid & 15) * 8) * 4);

    const int nch = kspan >> 6;

#define GISS(ci) do { \
    int _s = (ci) % 3; int _k0 = (ci) << 6; \
    uint32_t _ad = adst0 + _s * STGW * 4; \
    const __half* _a = Ab + _k0; \
    cp16(_ad,      _a);      cp16(_ad + 16, _a + 8); \
    cp16(_ad + 32, _a + 16); cp16(_ad + 48, _a + 24); \
    const uint32_t* _bs = Bb + (size_t)(_k0 >> 1) * N; \
    uint32_t _bd = bdst0 + _s * STGW * 4; \
    cp16(_bd,      _bs);     cp16(_bd + 16, _bs + 4); \
    cp16(_bd + 16 * BW * 4,      _bs + (size_t)16 * N); \
    cp16(_bd + 16 * BW * 4 + 16, _bs + (size_t)16 * N + 4); \
} while (0)

    // prologue: 2 chunks in flight
    if (0 < nch) GISS(0);
    cp_commit();
    if (1 < nch) GISS(1);
    cp_commit();

    for (int ci = 0; ci < nch; ci++) {
        cp_wait<1>();
        __syncthreads();
        if (ci + 2 < nch) GISS(ci + 2);
        cp_commit();

        const uint32_t* uA = usm + (ci % 3) * STGW;
        const uint32_t* uB = uA + ABUFW;
#pragma unroll
        for (int ks = 0; ks < 4; ks++) {
            int kbw = ks * 8;
            uint32_t af[4][4], bf[4][2];
#pragma unroll
            for (int mi = 0; mi < 4; mi++) {
                int mr = wm * 64 + mi * 16 + lg;
                af[mi][0] = uA[mr * AW + kbw + lq];
                af[mi][1] = uA[(mr + 8) * AW + kbw + lq];
                af[mi][2] = uA[mr * AW + kbw + 4 + lq];
                af[mi][3] = uA[(mr + 8) * AW + kbw + 4 + lq];
            }
#pragma unroll
            for (int ni = 0; ni < 4; ni++) {
                int nc = wn * 32 + ni * 8 + lg;
                bf[ni][0] = uB[(kbw + lq) * BW + nc];
                bf[ni][1] = uB[(kbw + 4 + lq) * BW + nc];
            }
#pragma unroll
            for (int mi = 0; mi < 4; mi++)
#pragma unroll
                for (int ni = 0; ni < 4; ni++)
                    mma_fp16(acc[mi][ni], af[mi], bf[ni]);
        }
    }
#undef GISS

    if (MODE == EPI_QKV) {
        __half* out = (__half*)Cv;
#pragma unroll
        for (int mi = 0; mi < 4; mi++) {
#pragma unroll
            for (int hf = 0; hf < 2; hf++) {
                int r = row0 + wm * 64 + mi * 16 + lg + hf * 8;
                int bI = r >> 10, t = r & (Tn - 1);
                float v[4][2];
#pragma unroll
                for (int ni = 0; ni < 4; ni++) {
                    int c = col0 + wn * 32 + ni * 8 + lq * 2;
                    v[ni][0] = acc[mi][ni][hf * 2 + 0] + bias[c];
                    v[ni][1] = acc[mi][ni][hf * 2 + 1] + bias[c + 1];
                }
                if (qkvmode == 0 && !(wn & 1)) {
#pragma unroll
                    for (int ni = 0; ni < 2; ni++) {
                        int d0 = ni * 8 + lq * 2;
#pragma unroll
                        for (int j = 0; j < 2; j++) {
                            float ang = (float)t * exp2f(-0.625f * (float)(d0 + j));
                            float sv, cv;
                            sincosf(ang, &sv, &cv);
                            float a = v[ni][j], b2 = v[ni + 2][j];
                            v[ni][j]     = a * cv - b2 * sv;
                            v[ni + 2][j] = b2 * cv + a * sv;
                        }
                    }
                }
#pragma unroll
                for (int ni = 0; ni < 4; ni++) {
                    int c = col0 + wn * 32 + ni * 8 + lq * 2;
                    int h = c >> 6, d = c & 63;
                    size_t base = ((size_t)bI * Hn + h) * ((size_t)Tn * HSn);
                    __half2 h2 = __floats2half2_rn(v[ni][0], v[ni][1]);
                    if (qkvmode != 2) {
                        *(__half2*)(out + base + (size_t)t * HSn + d) = h2;
                    } else {
                        size_t w = base + ((size_t)(t >> 1) * HSn + d) * 2 + (t & 1);
                        out[w]     = __low2half(h2);
                        out[w + 2] = __high2half(h2);
                    }
                }
            }
        }
    } else {
        float* out = (float*)Cv;
#pragma unroll
        for (int mi = 0; mi < 4; mi++)
#pragma unroll
            for (int ni = 0; ni < 4; ni++)
#pragma unroll
                for (int hf = 0; hf < 2; hf++) {
                    int r = row0 + wm * 64 + mi * 16 + lg + hf * 8;
                    int c = col0 + wn * 32 + ni * 8 + lq * 2;
                    size_t oi = (size_t)r * N + c;
                    out[oi]     = acc[mi][ni][hf * 2 + 0];
                    out[oi + 1] = acc[mi][ni][hf * 2 + 1];
                }
    }
}

struct QKVArgs {
    const float *b0, *b1, *b2;
    __half *q, *k, *v;
};

__global__ __launch_bounds__(256, 2)
void gemm_qkv(const __half* __restrict__ A, QKVArgs a) {
    extern __shared__ uint32_t usm[];
    int z = blockIdx.z;
    const uint32_t* Bp = g_wh + (size_t)z * (512 * 1024);
    const float* bias = (z == 0) ? a.b0 : (z == 1) ? a.b1 : a.b2;
    __half* out = (z == 0) ? a.q : (z == 1) ? a.k : a.v;
    gemm_body<EPI_QKV>(usm, A, Bp, bias, out, Cn, Cn, 0, Cn,
                       blockIdx.y * 128, blockIdx.x * 128, (z == 2) ? 2 : 0);
}

__global__ __launch_bounds__(256, 2)
void gemm_splitk(const __half* __restrict__ A, const uint32_t* __restrict__ Bp,
                 float* __restrict__ P, int N, int Kfull) {
    extern __shared__ uint32_t usm[];
    int z = blockIdx.z;
    int kh = Kfull >> 1;
    float* out = P + (size_t)z * (Bn * Tn) * Cn;
    gemm_body<EPI_NONE>(usm, A, Bp, nullptr, out, N, Kfull, z * kh, kh,
                        blockIdx.y * 128, blockIdx.x * 128, -1);
}

// ================= dual FFN-up GEMM (K-chunk 64, 2-stage) ===================
#define DUAL_SMEMW (2*ABUFW + 4*BBUFW)

__global__ __launch_bounds__(256)
void gemm_ffn_dual(const __half* __restrict__ A,
                   const uint32_t* __restrict__ B1p,
                   const uint32_t* __restrict__ B2p,
                   const float* __restrict__ bias1,
                   const float* __restrict__ bias2,
                   __half* __restrict__ C) {
    extern __shared__ uint32_t usm[];
    const int N = FFNn, K = Cn;
    uint32_t sb = smem_u32(usm);
    int tid = threadIdx.x;
    int lane = tid & 31, wid = tid >> 5;
    int wm = wid >> 2, wn = wid & 3;
    int lg = lane >> 2, lq = lane & 3;
    int row0 = blockIdx.y * 128, col0 = blockIdx.x * 128;

    float acc1[4][4][4] = {};
    float acc2[4][4][4] = {};

    int aw = (tid & 1) * 16;
    const __half* Ab = A + (size_t)(row0 + (tid >> 1)) * K + aw * 2;
    const uint32_t* B1b = B1p + (size_t)(tid >> 4) * N + col0 + (tid & 15) * 8;
    const uint32_t* B2b = B2p + (size_t)(tid >> 4) * N + col0 + (tid & 15) * 8;
    uint32_t adst0 = sb + (uint32_t)(((tid >> 1) * AW + aw) * 4);
    uint32_t b1dst0 = sb + (uint32_t)((2 * ABUFW + (tid >> 4) * BW + (tid & 15) * 8) * 4);
    uint32_t b2dst0 = b1dst0 + 2 * BBUFW * 4;

    const int nch = K >> 6;

#define DISS(ci) do { \
    int _p = (ci) & 1; int _k0 = (ci) << 6; \
    uint32_t _ad = adst0 + _p * ABUFW * 4; \
    const __half* _a = Ab + _k0; \
    cp16(_ad,      _a);      cp16(_ad + 16, _a + 8); \
    cp16(_ad + 32, _a + 16); cp16(_ad + 48, _a + 24); \
    size_t _bo = (size_t)(_k0 >> 1) * N; \
    uint32_t _b1d = b1dst0 + _p * BBUFW * 4; \
    cp16(_b1d,      B1b + _bo);     cp16(_b1d + 16, B1b + _bo + 4); \
    cp16(_b1d + 16 * BW * 4,      B1b + _bo + (size_t)16 * N); \
    cp16(_b1d + 16 * BW * 4 + 16, B1b + _bo + (size_t)16 * N + 4); \
    uint32_t _b2d = b2dst0 + _p * BBUFW * 4; \
    cp16(_b2d,      B2b + _bo);     cp16(_b2d + 16, B2b + _bo + 4); \
    cp16(_b2d + 16 * BW * 4,      B2b + _bo + (size_t)16 * N); \
    cp16(_b2d + 16 * BW * 4 + 16, B2b + _bo + (size_t)16 * N + 4); \
} while (0)

    DISS(0); cp_commit();

    for (int ci = 0; ci < nch; ci++) {
        cp_wait<0>();
        __syncthreads();
        if (ci + 1 < nch) { DISS(ci + 1); cp_commit(); }

        const uint32_t* uA  = usm + (ci & 1) * ABUFW;
        const uint32_t* uB1 = usm + 2 * ABUFW + (ci & 1) * BBUFW;
        const uint32_t* uB2 = uB1 + 2 * BBUFW;
#pragma unroll
        for (int ks = 0; ks < 4; ks++) {
            int kbw = ks * 8;
            uint32_t af[4][4], bf1[4][2], bf2[4][2];
#pragma unroll
            for (int mi = 0; mi < 4; mi++) {
                int mr = wm * 64 + mi * 16 + lg;
                af[mi][0] = uA[mr * AW + kbw + lq];
                af[mi][1] = uA[(mr + 8) * AW + kbw + lq];
                af[mi][2] = uA[mr * AW + kbw + 4 + lq];
                af[mi][3] = uA[(mr + 8) * AW + kbw + 4 + lq];
            }
#pragma unroll
            for (int ni = 0; ni < 4; ni++) {
                int nc = wn * 32 + ni * 8 + lg;
                bf1[ni][0] = uB1[(kbw + lq) * BW + nc];
                bf1[ni][1] = uB1[(kbw + 4 + lq) * BW + nc];
                bf2[ni][0] = uB2[(kbw + lq) * BW + nc];
                bf2[ni][1] = uB2[(kbw + 4 + lq) * BW + nc];
            }
#pragma unroll
            for (int mi = 0; mi < 4; mi++)
#pragma unroll
                for (int ni = 0; ni < 4; ni++) {
                    mma_fp16(acc1[mi][ni], af[mi], bf1[ni]);
                    mma_fp16(acc2[mi][ni], af[mi], bf2[ni]);
                }
        }
        __syncthreads();
    }
#undef DISS

#pragma unroll
    for (int mi = 0; mi < 4; mi++) {
#pragma unroll
        for (int ni = 0; ni < 4; ni++) {
#pragma unroll
            for (int hf = 0; hf < 2; hf++) {
                int r = row0 + wm * 64 + mi * 16 + lg + hf * 8;
                int c = col0 + wn * 32 + ni * 8 + lq * 2;
                float k0 = acc1[mi][ni][hf * 2 + 0] + bias1[c];
                float k1 = acc1[mi][ni][hf * 2 + 1] + bias1[c + 1];
                float m0 = acc2[mi][ni][hf * 2 + 0] + bias2[c];
                float m1 = acc2[mi][ni][hf * 2 + 1] + bias2[c + 1];
                float gl0 = 0.5f * k0 * (1.f + erff(k0 * 0.70710678118654752f));
                float gl1 = 0.5f * k1 * (1.f + erff(k1 * 0.70710678118654752f));
                *(__half2*)(C + (size_t)r * FFNn + c) =
                    __floats2half2_rn(gl0 * m0, gl1 * m1);
            }
        }
    }
}

// finalize Wgw
__global__ void fin_wgw(const float* __restrict__ P, const float* __restrict__ bgw,
                        const float* __restrict__ x1, float* __restrict__ out) {
    size_t i = ((size_t)blockIdx.x * 256 + threadIdx.x) * 4;
    const size_t half = (size_t)(Bn * Tn) * Cn;
    float4 a = *(const float4*)(P + i);
    float4 b = *(const float4*)(P + half + i);
    float4 r = *(const float4*)(x1 + i);
    int c = (int)(i & (Cn - 1));
    float4 o;
    o.x = a.x + b.x + bgw[c]     + r.x;
    o.y = a.y + b.y + bgw[c + 1] + r.y;
    o.z = a.z + b.z + bgw[c + 2] + r.z;
    o.w = a.w + b.w + bgw[c + 3] + r.w;
    *(float4*)(out + i) = o;
}

// ---------------- scores via fp16 mma (NT, triangular grid) ----------------
#define SW 36
__global__ __launch_bounds__(256, 2)
void scores_mma() {
    int i = blockIdx.x;
    int tt = (int)((sqrtf(8.f * (float)i + 1.f) - 1.f) * 0.5f);
    while ((tt + 1) * (tt + 2) / 2 <= i) tt++;
    while (tt * (tt + 1) / 2 > i) tt--;
    int ut = i - tt * (tt + 1) / 2;
    int z = blockIdx.y;
    int row0 = tt * 128, col0 = ut * 128;
    const __half* q = g_q + (size_t)z * Tn * HSn;
    const __half* k = g_k + (size_t)z * Tn * HSn;

    __shared__ uint32_t sq[128 * SW];
    __shared__ uint32_t sk[128 * SW];

    int tid = threadIdx.x;
    int lane = tid & 31, wid = tid >> 5;
    int wm = wid >> 2, wn = wid & 3;
    int lg = lane >> 2, lq = lane & 3;

#pragma unroll
    for (int it = 0; it < 4; it++) {
        int id = it * 256 + tid;
        int row = id >> 3, c8 = id & 7;
        *(uint4*)&sq[row * SW + c8 * 4] =
            *(const uint4*)(q + (size_t)(row0 + row) * HSn + c8 * 8);
        *(uint4*)&sk[row * SW + c8 * 4] =
            *(const uint4*)(k + (size_t)(col0 + row) * HSn + c8 * 8);
    }
    __syncthreads();

    float acc[4][4][4] = {};
#pragma unroll
    for (int ks = 0; ks < 4; ks++) {
        int kbw = ks * 8;
        uint32_t af[4][4], bf[4][2];
#pragma unroll
        for (int mi = 0; mi < 4; mi++) {
            int mr = wm * 64 + mi * 16 + lg;
            af[mi][0] = sq[mr * SW + kbw + lq];
            af[mi][1] = sq[(mr + 8) * SW + kbw + lq];
            af[mi][2] = sq[mr * SW + kbw + 4 + lq];
            af[mi][3] = sq[(mr + 8) * SW + kbw + 4 + lq];
        }
#pragma unroll
        for (int ni = 0; ni < 4; ni++) {
            int nc = wn * 32 + ni * 8 + lg;
            bf[ni][0] = sk[nc * SW + kbw + lq];
            bf[ni][1] = sk[nc * SW + kbw + 4 + lq];
        }
#pragma unroll
        for (int mi = 0; mi < 4; mi++)
#pragma unroll
            for (int ni = 0; ni < 4; ni++)
                mma_fp16(acc[mi][ni], af[mi], bf[ni]);
    }

    __half* out = g_att + (size_t)z * Tn * Tn;
#pragma unroll
    for (int mi = 0; mi < 4; mi++)
#pragma unroll
        for (int ni = 0; ni < 4; ni++)
#pragma unroll
            for (int hf = 0; hf < 2; hf++) {
                int r = row0 + wm * 64 + mi * 16 + lg + hf * 8;
                int c = col0 + wn * 32 + ni * 8 + lq * 2;
                *(__half2*)(out + (size_t)r * Tn + c) =
                    __floats2half2_rn(acc[mi][ni][hf * 2 + 0] * 0.125f,
                                      acc[mi][ni][hf * 2 + 1] * 0.125f);
            }
}

// ---------------- fused softmax (causal) * w + head-mix (R10 version) -------
#define SMIX_SMEM ((Hn*Tn + 256) * 4)
__global__ __launch_bounds__(256)
void softmax_mix(const float* __restrict__ time_w,
                 const float* __restrict__ alpha,
                 const float* __restrict__ beta,
                 const float* __restrict__ Wmix) {
    extern __shared__ float sm[];
    float* p  = sm;
    float* wm = sm + Hn * Tn;
    int t = blockIdx.x, b = blockIdx.y;
    int tid = threadIdx.x, lane = tid & 31, w = tid >> 5;
    if (tid < 256) wm[tid] = Wmix[tid];
    int len = t + 1;

#pragma unroll
    for (int hh = 0; hh < 2; hh++) {
        int h = w * 2 + hh;
        const __half* src = g_att + (((size_t)b * Hn + h) * Tn + t) * Tn;
        float* ph = p + h * Tn;
        float mx = -1e30f;
        for (int u = lane; u < len; u += 32) {
            float v = __half2float(src[u]); ph[u] = v; mx = fmaxf(mx, v);
        }
#pragma unroll
        for (int o = 16; o; o >>= 1) mx = fmaxf(mx, __shfl_xor_sync(0xFFFFFFFFu, mx, o));
        float sum = 0.f;
        for (int u = lane; u < len; u += 32) {
            float e = expf(ph[u] - mx); ph[u] = e; sum += e;
        }
#pragma unroll
        for (int o = 16; o; o >>= 1) sum += __shfl_xor_sync(0xFFFFFFFFu, sum, o);
        float inv = 1.f / sum;
        float bt = beta[h * Tn + t];
        const float* twr = time_w + h * TTn + (TTn - 1 - t);
        const float* alr = alpha + h * Tn;
        for (int u = lane; u < len; u += 32)
            ph[u] *= inv * twr[u] * alr[u] * bt;
    }
    __syncthreads();

    int zend = (t / 128) * 128 + 128;
    const size_t stride = (size_t)Tn * Tn;
    for (int u = tid; u < zend; u += 256) {
        size_t obase = (((size_t)b * Hn) * Tn + t) * Tn + u;
        if (u < len) {
            float vals[Hn];
#pragma unroll
            for (int j = 0; j < Hn; j++) vals[j] = p[j * Tn + u];
#pragma unroll
            for (int i = 0; i < Hn; i++) {
                float s = 0.f;
#pragma unroll
                for (int j = 0; j < Hn; j++) s += wm[i * Hn + j] * vals[j];
                g_att2[obase + i * stride] = __float2half(s);
            }
        } else {
#pragma unroll
            for (int i = 0; i < Hn; i++)
                g_att2[obase + i * stride] = __float2half(0.f);
        }
    }
}

// ---------------- y = att2 @ v via fp16 mma (R10 version) -------------------
#define AVW 20
#define VW 72
__global__ __launch_bounds__(256, 2)
void av_mma() {
    __shared__ uint32_t sa2[128 * AVW];
    __shared__ uint32_t sv [16 * VW];
    int tt = blockIdx.x;
    int z  = blockIdx.y;
    int row0 = tt * 128;
    const __half* Am = g_att2 + (size_t)z * Tn * Tn;
    const uint32_t* Vw = (const uint32_t*)g_v + (size_t)z * (Tn * HSn / 2);

    int tid = threadIdx.x;
    int lane = tid & 31, wid = tid >> 5;
    int wm2 = wid >> 1;
    int wn2 = wid & 1;
    int lg = lane >> 2, lq = lane & 3;

    float acc[2][4][4] = {};

    int ar = tid >> 1, ac8 = (tid & 1) * 2;
    int vr = tid >> 4, vc = tid & 15;

    int klim = row0 + 128;
    for (int k0 = 0; k0 < klim; k0 += 32) {
#pragma unroll
        for (int j = 0; j < 2; j++)
            *(uint4*)&sa2[ar * AVW + (ac8 + j) * 4] =
                *(const uint4*)(Am + (size_t)(row0 + ar) * Tn + k0 + (ac8 + j) * 8);
        *(uint4*)&sv[vr * VW + vc * 4] =
            *(const uint4*)(Vw + ((size_t)((k0 >> 1) + vr)) * HSn + vc * 4);
        __syncthreads();
#pragma unroll
        for (int ks = 0; ks < 2; ks++) {
            int kbw = ks * 8;
            uint32_t af[2][4], bf[4][2];
#pragma unroll
            for (int mi = 0; mi < 2; mi++) {
                int mr = wm2 * 32 + mi * 16 + lg;
                af[mi][0] = sa2[mr * AVW + kbw + lq];
                af[mi][1] = sa2[(mr + 8) * AVW + kbw + lq];
                af[mi][2] = sa2[mr * AVW + kbw + 4 + lq];
                af[mi][3] = sa2[(mr + 8) * AVW + kbw + 4 + lq];
            }
#pragma unroll
            for (int ni = 0; ni < 4; ni++) {
                int nc = wn2 * 32 + ni * 8 + lg;
                bf[ni][0] = sv[(kbw + lq) * VW + nc];
                bf[ni][1] = sv[(kbw + 4 + lq) * VW + nc];
            }
#pragma unroll
            for (int mi = 0; mi < 2; mi++)
#pragma unroll
                for (int ni = 0; ni < 4; ni++)
                    mma_fp16(acc[mi][ni], af[mi], bf[ni]);
        }
        __syncthreads();
    }

    int b = z / Hn, h = z % Hn;
#pragma unroll
    for (int mi = 0; mi < 2; mi++)
#pragma unroll
        for (int ni = 0; ni < 4; ni++)
#pragma unroll
            for (int hf = 0; hf < 2; hf++) {
                int t = row0 + wm2 * 32 + mi * 16 + lg + hf * 8;
                int d = wn2 * 32 + ni * 8 + lq * 2;
                size_t oi = ((size_t)b * Tn + t) * Cn + h * HSn + d;
                *(__half2*)(g_y + oi) =
                    __floats2half2_rn(acc[mi][ni][hf * 2 + 0],
                                      acc[mi][ni][hf * 2 + 1]);
            }
}

// ---------------- launch ----------------
extern "C" void kernel_launch(void* const* d_in, const int* in_sizes, int n_in,
                              void* d_out, int out_size) {
    const float* x         = (const float*)d_in[0];
    const float* ln1_g     = (const float*)d_in[1];
    const float* ln1_b     = (const float*)d_in[2];
    const float* Wq        = (const float*)d_in[3];
    const float* bq        = (const float*)d_in[4];
    const float* Wk        = (const float*)d_in[5];
    const float* bk        = (const float*)d_in[6];
    const float* Wv        = (const float*)d_in[7];
    const float* bv        = (const float*)d_in[8];
    const float* Wo        = (const float*)d_in[9];
    const float* bo        = (const float*)d_in[10];
    const float* time_w    = (const float*)d_in[11];
    const float* time_alpha= (const float*)d_in[12];
    const float* time_beta = (const float*)d_in[13];
    const float* time_gamma= (const float*)d_in[14];
    const float* Wmix      = (const float*)d_in[15];
    const float* ln2_g     = (const float*)d_in[16];
    const float* ln2_b     = (const float*)d_in[17];
    const float* Wgk       = (const float*)d_in[18];
    const float* bgk       = (const float*)d_in[19];
    const float* Wgv       = (const float*)d_in[20];
    const float* bgv       = (const float*)d_in[21];
    const float* Wgw       = (const float*)d_in[22];
    const float* bgw       = (const float*)d_in[23];

    __half *xs, *q, *k, *v, *gvb, *yb, *atth, *xmp;
    float *x1;
    uint32_t* wh;
    cudaGetSymbolAddress((void**)&xs,  g_xs);
    cudaGetSymbolAddress((void**)&q,   g_q);
    cudaGetSymbolAddress((void**)&k,   g_k);
    cudaGetSymbolAddress((void**)&v,   g_v);
    cudaGetSymbolAddress((void**)&yb,  g_y);
    cudaGetSymbolAddress((void**)&x1,  g_x1);
    cudaGetSymbolAddress((void**)&gvb, g_gv);
    cudaGetSymbolAddress((void**)&atth, g_att);
    cudaGetSymbolAddress((void**)&wh,  g_wh);
    cudaGetSymbolAddress((void**)&xmp, g_xm);
    float* part = (float*)atth;

    static bool attr_done = false;
    if (!attr_done) {
        cudaFuncSetAttribute(softmax_mix, cudaFuncAttributeMaxDynamicSharedMemorySize, SMIX_SMEM);
        cudaFuncSetAttribute(gemm_qkv,    cudaFuncAttributeMaxDynamicSharedMemorySize, GEMM_SMEMW * 4);
        cudaFuncSetAttribute(gemm_splitk, cudaFuncAttributeMaxDynamicSharedMemorySize, GEMM_SMEMW * 4);
        cudaFuncSetAttribute(gemm_ffn_dual, cudaFuncAttributeMaxDynamicSharedMemorySize, DUAL_SMEMW * 4);
        attr_done = true;
    }

    const int M = Bn * Tn;   // 2048

    // 0) weight conversion to packed fp16
    W4 w4; w4.w[0] = Wq; w4.w[1] = Wk; w4.w[2] = Wv; w4.w[3] = Wo;
    conv_cc<<<dim3(4, 512, 4), 256>>>(w4);
    conv_cf<<<dim3(16, 512, 2), 256>>>(Wgk, Wgv);
    conv_fc<<<dim3(4, 2048), 256>>>(Wgw);

    // 1) LN1 + time shift
    ln1_shift_kernel<<<Bn * Tn, 256>>>(x, ln1_g, ln1_b);

    // 2) QKV fused; rotary fused; v k-packed
    QKVArgs qa = {bq, bk, bv, q, k, v};
    gemm_qkv<<<dim3(Cn / 128, M / 128, 3), 256, GEMM_SMEMW * 4>>>(xs, qa);

    // 3) scores (triangular grid)
    scores_mma<<<dim3(36, Bn * Hn), 256>>>();

    // 4) softmax * w + head mix
    softmax_mix<<<dim3(Tn, Bn), 256, SMIX_SMEM>>>(time_w, time_alpha, time_beta, Wmix);

    // 5) y = att2 @ v
    av_mma<<<dim3(Tn / 128, Bn * Hn), 256>>>();

    // 6) out projection: split-K=2, fused finalize+LN2
    gemm_splitk<<<dim3(Cn / 128, M / 128, 2), 256, GEMM_SMEMW * 4>>>(
        yb, wh + WOFF_O, part, Cn, Cn);
    ln2_fused<<<Bn * Tn, 256>>>(part, bo, time_gamma, x, ln2_g, ln2_b);

    // 7) FFN up: dual GEMM
    gemm_ffn_dual<<<dim3(FFNn / 128, M / 128), 256, DUAL_SMEMW * 4>>>(
        xmp, wh + WOFF_GK, wh + WOFF_GV, bgk, bgv, gvb);

    // 8) FFN down: split-K=2 + finalize
    gemm_splitk<<<dim3(Cn / 128, M / 128, 2), 256, GEMM_SMEMW * 4>>>(
        gvb, wh + WOFF_GW, part, Cn, FFNn);
    fin_wgw<<<(M * Cn) / (256 * 4), 256>>>(part, bgw, x1, (float*)d_out);
}

// round 13
// speedup vs baseline: 1.0333x; 1.0333x over previous
#include <cuda_runtime.h>
#include <cuda_fp16.h>
#include <cstdint>
#include <math.h>

#define Bn   2
#define Tn   1024
#define Cn   1024
#define Hn   16
#define HSn  64
#define TTn  1024
#define FFNn 4096
#define EPSn 1e-6f

// ---------------- scratch ----------------
__device__ __half g_xs [Bn*Tn*Cn];
__device__ __half g_q  [Bn*Tn*Cn];
__device__ __half g_k  [Bn*Tn*Cn];
__device__ __half g_v  [Bn*Tn*Cn];          // k-pair packed per (b,h)
__device__ __half g_att [Bn*Hn*Tn*Tn];      // aliased as fp32 split-K partials
__device__ __half g_att2[Bn*Hn*Tn*Tn];
__device__ __half g_y  [Bn*Tn*Cn];
__device__ float  g_x1 [Bn*Tn*Cn];
__device__ __half g_xm [Bn*Tn*Cn];
__device__ __half g_gv [Bn*Tn*FFNn];
__device__ uint32_t g_wh[8*1024*1024];      // packed half2 weights, 32MB

#define WOFF_Q   0
#define WOFF_K   (512*1024)
#define WOFF_V   (2*512*1024)
#define WOFF_O   (3*512*1024)
#define WOFF_GK  (4*512*1024)
#define WOFF_GV  (WOFF_GK + 512*4096)
#define WOFF_GW  (WOFF_GV + 512*4096)

// ---------------- helpers ----------------
__device__ __forceinline__ void mma_fp16(float* d, const uint32_t* a, const uint32_t* b) {
    asm volatile(
        "mma.sync.aligned.m16n8k16.row.col.f32.f16.f16.f32 "
        "{%0,%1,%2,%3}, {%4,%5,%6,%7}, {%8,%9}, {%0,%1,%2,%3};"
        : "+f"(d[0]), "+f"(d[1]), "+f"(d[2]), "+f"(d[3])
        : "r"(a[0]), "r"(a[1]), "r"(a[2]), "r"(a[3]), "r"(b[0]), "r"(b[1]));
}
__device__ __forceinline__ uint32_t smem_u32(const void* p) {
    uint32_t a;
    asm("{ .reg .u64 t; cvta.to.shared.u64 t, %1; cvt.u32.u64 %0, t; }"
        : "=r"(a) : "l"(p));
    return a;
}
__device__ __forceinline__ void cp16(uint32_t dst, const void* src) {
    asm volatile("cp.async.ca.shared.global [%0], [%1], 16;" :: "r"(dst), "l"(src));
}
__device__ __forceinline__ void cp_commit() {
    asm volatile("cp.async.commit_group;" ::: "memory");
}
template<int N> __device__ __forceinline__ void cp_wait() {
    asm volatile("cp.async.wait_group %0;" :: "n"(N) : "memory");
}

// ---------------- weight conversion ----------------
struct W4 { const float* w[4]; };
__global__ void conv_cc(W4 ws) {
    int z = blockIdx.z;
    const float* W = ws.w[z];
    uint32_t* dst = g_wh + (size_t)z * (512*1024);
    int n  = blockIdx.x * 256 + threadIdx.x;
    int k2 = blockIdx.y;
    __half2 h = __floats2half2_rn(W[(size_t)(2*k2) * Cn + n],
                                  W[(size_t)(2*k2+1) * Cn + n]);
    dst[(size_t)k2 * Cn + n] = *(uint32_t*)&h;
}
__global__ void conv_cf(const float* W0, const float* W1) {
    int z = blockIdx.z;
    const float* W = z ? W1 : W0;
    uint32_t* dst = g_wh + WOFF_GK + (size_t)z * (512*4096);
    int n  = blockIdx.x * 256 + threadIdx.x;
    int k2 = blockIdx.y;
    __half2 h = __floats2half2_rn(W[(size_t)(2*k2) * FFNn + n],
                                  W[(size_t)(2*k2+1) * FFNn + n]);
    dst[(size_t)k2 * FFNn + n] = *(uint32_t*)&h;
}
__global__ void conv_fc(const float* W) {
    uint32_t* dst = g_wh + WOFF_GW;
    int n  = blockIdx.x * 256 + threadIdx.x;
    int k2 = blockIdx.y;
    __half2 h = __floats2half2_rn(W[(size_t)(2*k2) * Cn + n],
                                  W[(size_t)(2*k2+1) * Cn + n]);
    dst[(size_t)k2 * Cn + n] = *(uint32_t*)&h;
}

// ---------------- fast row reduce ----------------
__device__ __forceinline__ void row_stats(float4 v4, float& mean, float& rstd,
                                          float* red) {
    int tid = threadIdx.x, lane = tid & 31, w = tid >> 5;
    float s  = v4.x + v4.y + v4.z + v4.w;
    float s2 = v4.x*v4.x + v4.y*v4.y + v4.z*v4.z + v4.w*v4.w;
#pragma unroll
    for (int o = 16; o; o >>= 1) {
        s  += __shfl_xor_sync(0xFFFFFFFFu, s,  o);
        s2 += __shfl_xor_sync(0xFFFFFFFFu, s2, o);
    }
    if (lane == 0) { red[w] = s; red[8 + w] = s2; }
    __syncthreads();
    if (tid == 0) {
        float a = 0.f, b2 = 0.f;
#pragma unroll
        for (int i = 0; i < 8; i++) { a += red[i]; b2 += red[8 + i]; }
        red[16] = a; red[17] = b2;
    }
    __syncthreads();
    mean = red[16] / Cn;
    rstd = rsqrtf(red[17] / Cn - mean * mean + EPSn);
}

// ---------------- LN1 + time_shift_half ----------------
__global__ __launch_bounds__(256)
void ln1_shift_kernel(const float* __restrict__ x,
                      const float* __restrict__ g,
                      const float* __restrict__ b) {
    __shared__ float red[18];
    int bt = blockIdx.x;
    int bb = bt >> 10, t = bt & (Tn - 1);
    int c = threadIdx.x * 4;
    float4 v4 = *(const float4*)(x + (size_t)bt * Cn + c);
    float mean, rstd;
    row_stats(v4, mean, rstd, red);
    float4 g4 = *(const float4*)(g + c);
    float4 b4 = *(const float4*)(b + c);
    __half2 h01 = __floats2half2_rn((v4.x - mean) * rstd * g4.x + b4.x,
                                    (v4.y - mean) * rstd * g4.y + b4.y);
    __half2 h23 = __floats2half2_rn((v4.z - mean) * rstd * g4.z + b4.z,
                                    (v4.w - mean) * rstd * g4.w + b4.w);
    uint2 pk; pk.x = *(uint32_t*)&h01; pk.y = *(uint32_t*)&h23;
    if (c < Cn / 2) {
        if (t + 1 < Tn)
            *(uint2*)(g_xs + ((size_t)bb * Tn + t + 1) * Cn + c) = pk;
        if (t == 0)
            *(uint2*)(g_xs + (size_t)bb * Tn * Cn + c) = make_uint2(0, 0);
    } else {
        *(uint2*)(g_xs + (size_t)bt * Cn + c) = pk;
    }
}

// ---------------- fused fin_wo + LN2 ----------------
__global__ __launch_bounds__(256)
void ln2_fused(const float* __restrict__ P, const float* __restrict__ bo,
               const float* __restrict__ gamma, const float* __restrict__ x,
               const float* __restrict__ g, const float* __restrict__ b) {
    __shared__ float red[18];
    int bt = blockIdx.x;
    int t = bt & (Tn - 1);
    int c = threadIdx.x * 4;
    const size_t half = (size_t)(Bn * Tn) * Cn;
    size_t i = (size_t)bt * Cn + c;
    float4 a4 = *(const float4*)(P + i);
    float4 p4 = *(const float4*)(P + half + i);
    float4 x4 = *(const float4*)(x + i);
    float4 bo4 = *(const float4*)(bo + c);
    float gm = gamma[t];
    float4 v4;
    v4.x = (a4.x + p4.x + bo4.x) * gm + x4.x;
    v4.y = (a4.y + p4.y + bo4.y) * gm + x4.y;
    v4.z = (a4.z + p4.z + bo4.z) * gm + x4.z;
    v4.w = (a4.w + p4.w + bo4.w) * gm + x4.w;
    *(float4*)(g_x1 + i) = v4;
    float mean, rstd;
    row_stats(v4, mean, rstd, red);
    float4 g4 = *(const float4*)(g + c);
    float4 b4 = *(const float4*)(b + c);
    __half2 h01 = __floats2half2_rn((v4.x - mean) * rstd * g4.x + b4.x,
                                    (v4.y - mean) * rstd * g4.y + b4.y);
    __half2 h23 = __floats2half2_rn((v4.z - mean) * rstd * g4.z + b4.z,
                                    (v4.w - mean) * rstd * g4.w + b4.w);
    uint2 pk; pk.x = *(uint32_t*)&h01; pk.y = *(uint32_t*)&h23;
    *(uint2*)(g_xm + i) = pk;
}

// ================= fp16 GEMM core (128x128, 8 warps, K-chunk 64, 2-stage) ===
#define EPI_NONE  0
#define EPI_QKV   1

#define AW 36
#define BW 136
#define ABUFW (128*AW)
#define BBUFW (32*BW)
#define GEMM_SMEMW (2*(ABUFW+BBUFW))

template<int MODE>
__device__ __forceinline__ void gemm_body(
    uint32_t* usm,
    const __half* __restrict__ A, const uint32_t* __restrict__ Bp,
    const float* __restrict__ bias, void* __restrict__ Cv,
    int N, int Kfull, int koff, int kspan,
    int row0, int col0, int qkvmode)
{
    uint32_t sb = smem_u32(usm);
    int tid = threadIdx.x;
    int lane = tid & 31, wid = tid >> 5;
    int wm = wid >> 2, wn = wid & 3;
    int lg = lane >> 2, lq = lane & 3;

    float acc[4][4][4] = {};

    int aw = (tid & 1) * 16;
    const __half* Ab = A + (size_t)(row0 + (tid >> 1)) * Kfull + koff + aw * 2;
    const uint32_t* Bb = Bp + ((size_t)(koff >> 1) + (tid >> 4)) * N + col0 + (tid & 15) * 8;
    uint32_t adst0 = sb + (uint32_t)(((tid >> 1) * AW + aw) * 4);
    uint32_t bdst0 = sb + (uint32_t)((2 * ABUFW + (tid >> 4) * BW + (tid & 15) * 8) * 4);

    const int nch = kspan >> 6;

#define GISS(ci) do { \
    int _p = (ci) & 1; int _k0 = (ci) << 6; \
    uint32_t _ad = adst0 + _p * ABUFW * 4; \
    const __half* _a = Ab + _k0; \
    cp16(_ad,      _a);      cp16(_ad + 16, _a + 8); \
    cp16(_ad + 32, _a + 16); cp16(_ad + 48, _a + 24); \
    const uint32_t* _bs = Bb + (size_t)(_k0 >> 1) * N; \
    uint32_t _bd = bdst0 + _p * BBUFW * 4; \
    cp16(_bd,      _bs);     cp16(_bd + 16, _bs + 4); \
    cp16(_bd + 16 * BW * 4,      _bs + (size_t)16 * N); \
    cp16(_bd + 16 * BW * 4 + 16, _bs + (size_t)16 * N + 4); \
} while (0)

    GISS(0); cp_commit();

    for (int ci = 0; ci < nch; ci++) {
        cp_wait<0>();
        __syncthreads();
        if (ci + 1 < nch) { GISS(ci + 1); cp_commit(); }

        const uint32_t* uA = usm + (ci & 1) * ABUFW;
        const uint32_t* uB = usm + 2 * ABUFW + (ci & 1) * BBUFW;
#pragma unroll
        for (int ks = 0; ks < 4; ks++) {
            int kbw = ks * 8;
            uint32_t af[4][4], bf[4][2];
#pragma unroll
            for (int mi = 0; mi < 4; mi++) {
                int mr = wm * 64 + mi * 16 + lg;
                af[mi][0] = uA[mr * AW + kbw + lq];
                af[mi][1] = uA[(mr + 8) * AW + kbw + lq];
                af[mi][2] = uA[mr * AW + kbw + 4 + lq];
                af[mi][3] = uA[(mr + 8) * AW + kbw + 4 + lq];
            }
#pragma unroll
            for (int ni = 0; ni < 4; ni++) {
                int nc = wn * 32 + ni * 8 + lg;
                bf[ni][0] = uB[(kbw + lq) * BW + nc];
                bf[ni][1] = uB[(kbw + 4 + lq) * BW + nc];
            }
#pragma unroll
            for (int mi = 0; mi < 4; mi++)
#pragma unroll
                for (int ni = 0; ni < 4; ni++)
                    mma_fp16(acc[mi][ni], af[mi], bf[ni]);
        }
        __syncthreads();
    }
#undef GISS

    if (MODE == EPI_QKV) {
        __half* out = (__half*)Cv;
#pragma unroll
        for (int mi = 0; mi < 4; mi++) {
#pragma unroll
            for (int hf = 0; hf < 2; hf++) {
                int r = row0 + wm * 64 + mi * 16 + lg + hf * 8;
                int bI = r >> 10, t = r & (Tn - 1);
                float v[4][2];
#pragma unroll
                for (int ni = 0; ni < 4; ni++) {
                    int c = col0 + wn * 32 + ni * 8 + lq * 2;
                    v[ni][0] = acc[mi][ni][hf * 2 + 0] + bias[c];
                    v[ni][1] = acc[mi][ni][hf * 2 + 1] + bias[c + 1];
                }
                if (qkvmode == 0 && !(wn & 1)) {
#pragma unroll
                    for (int ni = 0; ni < 2; ni++) {
                        int d0 = ni * 8 + lq * 2;
#pragma unroll
                        for (int j = 0; j < 2; j++) {
                            float ang = (float)t * exp2f(-0.625f * (float)(d0 + j));
                            float sv, cv;
                            sincosf(ang, &sv, &cv);
                            float a = v[ni][j], b2 = v[ni + 2][j];
                            v[ni][j]     = a * cv - b2 * sv;
                            v[ni + 2][j] = b2 * cv + a * sv;
                        }
                    }
                }
#pragma unroll
                for (int ni = 0; ni < 4; ni++) {
                    int c = col0 + wn * 32 + ni * 8 + lq * 2;
                    int h = c >> 6, d = c & 63;
                    size_t base = ((size_t)bI * Hn + h) * ((size_t)Tn * HSn);
                    __half2 h2 = __floats2half2_rn(v[ni][0], v[ni][1]);
                    if (qkvmode != 2) {
                        *(__half2*)(out + base + (size_t)t * HSn + d) = h2;
                    } else {
                        size_t w = base + ((size_t)(t >> 1) * HSn + d) * 2 + (t & 1);
                        out[w]     = __low2half(h2);
                        out[w + 2] = __high2half(h2);
                    }
                }
            }
        }
    } else {
        float* out = (float*)Cv;
#pragma unroll
        for (int mi = 0; mi < 4; mi++)
#pragma unroll
            for (int ni = 0; ni < 4; ni++)
#pragma unroll
                for (int hf = 0; hf < 2; hf++) {
                    int r = row0 + wm * 64 + mi * 16 + lg + hf * 8;
                    int c = col0 + wn * 32 + ni * 8 + lq * 2;
                    size_t oi = (size_t)r * N + c;
                    out[oi]     = acc[mi][ni][hf * 2 + 0];
                    out[oi + 1] = acc[mi][ni][hf * 2 + 1];
                }
    }
}

struct QKVArgs {
    const float *b0, *b1, *b2;
    __half *q, *k, *v;
};

__global__ __launch_bounds__(256, 2)
void gemm_qkv(const __half* __restrict__ A, QKVArgs a) {
    extern __shared__ uint32_t usm[];
    int z = blockIdx.z;
    const uint32_t* Bp = g_wh + (size_t)z * (512 * 1024);
    const float* bias = (z == 0) ? a.b0 : (z == 1) ? a.b1 : a.b2;
    __half* out = (z == 0) ? a.q : (z == 1) ? a.k : a.v;
    gemm_body<EPI_QKV>(usm, A, Bp, bias, out, Cn, Cn, 0, Cn,
                       blockIdx.y * 128, blockIdx.x * 128, (z == 2) ? 2 : 0);
}

__global__ __launch_bounds__(256, 2)
void gemm_splitk(const __half* __restrict__ A, const uint32_t* __restrict__ Bp,
                 float* __restrict__ P, int N, int Kfull) {
    extern __shared__ uint32_t usm[];
    int z = blockIdx.z;
    int kh = Kfull >> 1;
    float* out = P + (size_t)z * (Bn * Tn) * Cn;
    gemm_body<EPI_NONE>(usm, A, Bp, nullptr, out, N, Kfull, z * kh, kh,
                        blockIdx.y * 128, blockIdx.x * 128, -1);
}

// ================= dual FFN-up GEMM (K-chunk 64, 2-stage) ===================
#define DUAL_SMEMW (2*ABUFW + 4*BBUFW)

__global__ __launch_bounds__(256)
void gemm_ffn_dual(const __half* __restrict__ A,
                   const uint32_t* __restrict__ B1p,
                   const uint32_t* __restrict__ B2p,
                   const float* __restrict__ bias1,
                   const float* __restrict__ bias2,
                   __half* __restrict__ C) {
    extern __shared__ uint32_t usm[];
    const int N = FFNn, K = Cn;
    uint32_t sb = smem_u32(usm);
    int tid = threadIdx.x;
    int lane = tid & 31, wid = tid >> 5;
    int wm = wid >> 2, wn = wid & 3;
    int lg = lane >> 2, lq = lane & 3;
    int row0 = blockIdx.y * 128, col0 = blockIdx.x * 128;

    float acc1[4][4][4] = {};
    float acc2[4][4][4] = {};

    int aw = (tid & 1) * 16;
    const __half* Ab = A + (size_t)(row0 + (tid >> 1)) * K + aw * 2;
    const uint32_t* B1b = B1p + (size_t)(tid >> 4) * N + col0 + (tid & 15) * 8;
    const uint32_t* B2b = B2p + (size_t)(tid >> 4) * N + col0 + (tid & 15) * 8;
    uint32_t adst0 = sb + (uint32_t)(((tid >> 1) * AW + aw) * 4);
    uint32_t b1dst0 = sb + (uint32_t)((2 * ABUFW + (tid >> 4) * BW + (tid & 15) * 8) * 4);
    uint32_t b2dst0 = b1dst0 + 2 * BBUFW * 4;

    const int nch = K >> 6;

#define DISS(ci) do { \
    int _p = (ci) & 1; int _k0 = (ci) << 6; \
    uint32_t _ad = adst0 + _p * ABUFW * 4; \
    const __half* _a = Ab + _k0; \
    cp16(_ad,      _a);      cp16(_ad + 16, _a + 8); \
    cp16(_ad + 32, _a + 16); cp16(_ad + 48, _a + 24); \
    size_t _bo = (size_t)(_k0 >> 1) * N; \
    uint32_t _b1d = b1dst0 + _p * BBUFW * 4; \
    cp16(_b1d,      B1b + _bo);     cp16(_b1d + 16, B1b + _bo + 4); \
    cp16(_b1d + 16 * BW * 4,      B1b + _bo + (size_t)16 * N); \
    cp16(_b1d + 16 * BW * 4 + 16, B1b + _bo + (size_t)16 * N + 4); \
    uint32_t _b2d = b2dst0 + _p * BBUFW * 4; \
    cp16(_b2d,      B2b + _bo);     cp16(_b2d + 16, B2b + _bo + 4); \
    cp16(_b2d + 16 * BW * 4,      B2b + _bo + (size_t)16 * N); \
    cp16(_b2d + 16 * BW * 4 + 16, B2b + _bo + (size_t)16 * N + 4); \
} while (0)

    DISS(0); cp_commit();

    for (int ci = 0; ci < nch; ci++) {
        cp_wait<0>();
        __syncthreads();
        if (ci + 1 < nch) { DISS(ci + 1); cp_commit(); }

        const uint32_t* uA  = usm + (ci & 1) * ABUFW;
        const uint32_t* uB1 = usm + 2 * ABUFW + (ci & 1) * BBUFW;
        const uint32_t* uB2 = uB1 + 2 * BBUFW;
#pragma unroll
        for (int ks = 0; ks < 4; ks++) {
            int kbw = ks * 8;
            uint32_t af[4][4], bf1[4][2], bf2[4][2];
#pragma unroll
            for (int mi = 0; mi < 4; mi++) {
                int mr = wm * 64 + mi * 16 + lg;
                af[mi][0] = uA[mr * AW + kbw + lq];
                af[mi][1] = uA[(mr + 8) * AW + kbw + lq];
                af[mi][2] = uA[mr * AW + kbw + 4 + lq];
                af[mi][3] = uA[(mr + 8) * AW + kbw + 4 + lq];
            }
#pragma unroll
            for (int ni = 0; ni < 4; ni++) {
                int nc = wn * 32 + ni * 8 + lg;
                bf1[ni][0] = uB1[(kbw + lq) * BW + nc];
                bf1[ni][1] = uB1[(kbw + 4 + lq) * BW + nc];
                bf2[ni][0] = uB2[(kbw + lq) * BW + nc];
                bf2[ni][1] = uB2[(kbw + 4 + lq) * BW + nc];
            }
#pragma unroll
            for (int mi = 0; mi < 4; mi++)
#pragma unroll
                for (int ni = 0; ni < 4; ni++) {
                    mma_fp16(acc1[mi][ni], af[mi], bf1[ni]);
                    mma_fp16(acc2[mi][ni], af[mi], bf2[ni]);
                }
        }
        __syncthreads();
    }
#undef DISS

#pragma unroll
    for (int mi = 0; mi < 4; mi++) {
#pragma unroll
        for (int ni = 0; ni < 4; ni++) {
#pragma unroll
            for (int hf = 0; hf < 2; hf++) {
                int r = row0 + wm * 64 + mi * 16 + lg + hf * 8;
                int c = col0 + wn * 32 + ni * 8 + lq * 2;
                float k0 = acc1[mi][ni][hf * 2 + 0] + bias1[c];
                float k1 = acc1[mi][ni][hf * 2 + 1] + bias1[c + 1];
                float m0 = acc2[mi][ni][hf * 2 + 0] + bias2[c];
                float m1 = acc2[mi][ni][hf * 2 + 1] + bias2[c + 1];
                float gl0 = 0.5f * k0 * (1.f + erff(k0 * 0.70710678118654752f));
                float gl1 = 0.5f * k1 * (1.f + erff(k1 * 0.70710678118654752f));
                *(__half2*)(C + (size_t)r * FFNn + c) =
                    __floats2half2_rn(gl0 * m0, gl1 * m1);
            }
        }
    }
}

// finalize Wgw
__global__ void fin_wgw(const float* __restrict__ P, const float* __restrict__ bgw,
                        const float* __restrict__ x1, float* __restrict__ out) {
    size_t i = ((size_t)blockIdx.x * 256 + threadIdx.x) * 4;
    const size_t half = (size_t)(Bn * Tn) * Cn;
    float4 a = *(const float4*)(P + i);
    float4 b = *(const float4*)(P + half + i);
    float4 r = *(const float4*)(x1 + i);
    int c = (int)(i & (Cn - 1));
    float4 o;
    o.x = a.x + b.x + bgw[c]     + r.x;
    o.y = a.y + b.y + bgw[c + 1] + r.y;
    o.z = a.z + b.z + bgw[c + 2] + r.z;
    o.w = a.w + b.w + bgw[c + 3] + r.w;
    *(float4*)(out + i) = o;
}

// ---------------- scores via fp16 mma (NT, triangular grid) ----------------
#define SW 36
__global__ __launch_bounds__(256, 2)
void scores_mma() {
    int i = blockIdx.x;
    int tt = (int)((sqrtf(8.f * (float)i + 1.f) - 1.f) * 0.5f);
    while ((tt + 1) * (tt + 2) / 2 <= i) tt++;
    while (tt * (tt + 1) / 2 > i) tt--;
    int ut = i - tt * (tt + 1) / 2;
    int z = blockIdx.y;
    int row0 = tt * 128, col0 = ut * 128;
    const __half* q = g_q + (size_t)z * Tn * HSn;
    const __half* k = g_k + (size_t)z * Tn * HSn;

    __shared__ uint32_t sq[128 * SW];
    __shared__ uint32_t sk[128 * SW];

    int tid = threadIdx.x;
    int lane = tid & 31, wid = tid >> 5;
    int wm = wid >> 2, wn = wid & 3;
    int lg = lane >> 2, lq = lane & 3;

#pragma unroll
    for (int it = 0; it < 4; it++) {
        int id = it * 256 + tid;
        int row = id >> 3, c8 = id & 7;
        *(uint4*)&sq[row * SW + c8 * 4] =
            *(const uint4*)(q + (size_t)(row0 + row) * HSn + c8 * 8);
        *(uint4*)&sk[row * SW + c8 * 4] =
            *(const uint4*)(k + (size_t)(col0 + row) * HSn + c8 * 8);
    }
    __syncthreads();

    float acc[4][4][4] = {};
#pragma unroll
    for (int ks = 0; ks < 4; ks++) {
        int kbw = ks * 8;
        uint32_t af[4][4], bf[4][2];
#pragma unroll
        for (int mi = 0; mi < 4; mi++) {
            int mr = wm * 64 + mi * 16 + lg;
            af[mi][0] = sq[mr * SW + kbw + lq];
            af[mi][1] = sq[(mr + 8) * SW + kbw + lq];
            af[mi][2] = sq[mr * SW + kbw + 4 + lq];
            af[mi][3] = sq[(mr + 8) * SW + kbw + 4 + lq];
        }
#pragma unroll
        for (int ni = 0; ni < 4; ni++) {
            int nc = wn * 32 + ni * 8 + lg;
            bf[ni][0] = sk[nc * SW + kbw + lq];
            bf[ni][1] = sk[nc * SW + kbw + 4 + lq];
        }
#pragma unroll
        for (int mi = 0; mi < 4; mi++)
#pragma unroll
            for (int ni = 0; ni < 4; ni++)
                mma_fp16(acc[mi][ni], af[mi], bf[ni]);
    }

    __half* out = g_att + (size_t)z * Tn * Tn;
#pragma unroll
    for (int mi = 0; mi < 4; mi++)
#pragma unroll
        for (int ni = 0; ni < 4; ni++)
#pragma unroll
            for (int hf = 0; hf < 2; hf++) {
                int r = row0 + wm * 64 + mi * 16 + lg + hf * 8;
                int c = col0 + wn * 32 + ni * 8 + lq * 2;
                *(__half2*)(out + (size_t)r * Tn + c) =
                    __floats2half2_rn(acc[mi][ni][hf * 2 + 0] * 0.125f,
                                      acc[mi][ni][hf * 2 + 1] * 0.125f);
            }
}

// ---------------- fused softmax (causal) * w + head-mix ----------------
#define SMIX_SMEM ((Hn*Tn + 256) * 4)
__global__ __launch_bounds__(256)
void softmax_mix(const float* __restrict__ time_w,
                 const float* __restrict__ alpha,
                 const float* __restrict__ beta,
                 const float* __restrict__ Wmix) {
    extern __shared__ float sm[];
    float* p  = sm;
    float* wm = sm + Hn * Tn;
    int t = blockIdx.x, b = blockIdx.y;
    int tid = threadIdx.x, lane = tid & 31, w = tid >> 5;
    if (tid < 256) wm[tid] = Wmix[tid];
    int len = t + 1;

#pragma unroll
    for (int hh = 0; hh < 2; hh++) {
        int h = w * 2 + hh;
        const __half* src = g_att + (((size_t)b * Hn + h) * Tn + t) * Tn;
        float* ph = p + h * Tn;
        float mx = -1e30f;
        for (int u = lane; u < len; u += 32) {
            float v = __half2float(src[u]); ph[u] = v; mx = fmaxf(mx, v);
        }
#pragma unroll
        for (int o = 16; o; o >>= 1) mx = fmaxf(mx, __shfl_xor_sync(0xFFFFFFFFu, mx, o));
        float sum = 0.f;
        for (int u = lane; u < len; u += 32) {
            float e = expf(ph[u] - mx); ph[u] = e; sum += e;
        }
#pragma unroll
        for (int o = 16; o; o >>= 1) sum += __shfl_xor_sync(0xFFFFFFFFu, sum, o);
        float inv = 1.f / sum;
        float bt = beta[h * Tn + t];
        const float* twr = time_w + h * TTn + (TTn - 1 - t);
        const float* alr = alpha + h * Tn;
        for (int u = lane; u < len; u += 32)
            ph[u] *= inv * twr[u] * alr[u] * bt;
    }
    __syncthreads();

    int zend = (t / 128) * 128 + 128;
    const size_t stride = (size_t)Tn * Tn;
    for (int u = tid; u < zend; u += 256) {
        size_t obase = (((size_t)b * Hn) * Tn + t) * Tn + u;
        if (u < len) {
            float vals[Hn];
#pragma unroll
            for (int j = 0; j < Hn; j++) vals[j] = p[j * Tn + u];
#pragma unroll
            for (int i = 0; i < Hn; i++) {
                float s = 0.f;
#pragma unroll
                for (int j = 0; j < Hn; j++) s += wm[i * Hn + j] * vals[j];
                g_att2[obase + i * stride] = __float2half(s);
            }
        } else {
#pragma unroll
            for (int i = 0; i < Hn; i++)
                g_att2[obase + i * stride] = __float2half(0.f);
        }
    }
}

// ---------------- y = att2 @ v via fp16 mma ----------------
#define AVW 20
#define VW 72
__global__ __launch_bounds__(256, 2)
void av_mma() {
    __shared__ uint32_t sa2[128 * AVW];
    __shared__ uint32_t sv [16 * VW];
    int tt = blockIdx.x;
    int z  = blockIdx.y;
    int row0 = tt * 128;
    const __half* Am = g_att2 + (size_t)z * Tn * Tn;
    const uint32_t* Vw = (const uint32_t*)g_v + (size_t)z * (Tn * HSn / 2);

    int tid = threadIdx.x;
    int lane = tid & 31, wid = tid >> 5;
    int wm2 = wid >> 1;
    int wn2 = wid & 1;
    int lg = lane >> 2, lq = lane & 3;

    float acc[2][4][4] = {};

    int ar = tid >> 1, ac8 = (tid & 1) * 2;
    int vr = tid >> 4, vc = tid & 15;

    int klim = row0 + 128;
    for (int k0 = 0; k0 < klim; k0 += 32) {
#pragma unroll
        for (int j = 0; j < 2; j++)
            *(uint4*)&sa2[ar * AVW + (ac8 + j) * 4] =
                *(const uint4*)(Am + (size_t)(row0 + ar) * Tn + k0 + (ac8 + j) * 8);
        *(uint4*)&sv[vr * VW + vc * 4] =
            *(const uint4*)(Vw + ((size_t)((k0 >> 1) + vr)) * HSn + vc * 4);
        __syncthreads();
#pragma unroll
        for (int ks = 0; ks < 2; ks++) {
            int kbw = ks * 8;
            uint32_t af[2][4], bf[4][2];
#pragma unroll
            for (int mi = 0; mi < 2; mi++) {
                int mr = wm2 * 32 + mi * 16 + lg;
                af[mi][0] = sa2[mr * AVW + kbw + lq];
                af[mi][1] = sa2[(mr + 8) * AVW + kbw + lq];
                af[mi][2] = sa2[mr * AVW + kbw + 4 + lq];
                af[mi][3] = sa2[(mr + 8) * AVW + kbw + 4 + lq];
            }
#pragma unroll
            for (int ni = 0; ni < 4; ni++) {
                int nc = wn2 * 32 + ni * 8 + lg;
                bf[ni][0] = sv[(kbw + lq) * VW + nc];
                bf[ni][1] = sv[(kbw + 4 + lq) * VW + nc];
            }
#pragma unroll
            for (int mi = 0; mi < 2; mi++)
#pragma unroll
                for (int ni = 0; ni < 4; ni++)
                    mma_fp16(acc[mi][ni], af[mi], bf[ni]);
        }
        __syncthreads();
    }

    int b = z / Hn, h = z % Hn;
#pragma unroll
    for (int mi = 0; mi < 2; mi++)
#pragma unroll
        for (int ni = 0; ni < 4; ni++)
#pragma unroll
            for (int hf = 0; hf < 2; hf++) {
                int t = row0 + wm2 * 32 + mi * 16 + lg + hf * 8;
                int d = wn2 * 32 + ni * 8 + lq * 2;
                size_t oi = ((size_t)b * Tn + t) * Cn + h * HSn + d;
                *(__half2*)(g_y + oi) =
                    __floats2half2_rn(acc[mi][ni][hf * 2 + 0],
                                      acc[mi][ni][hf * 2 + 1]);
            }
}

// ---------------- launch ----------------
extern "C" void kernel_launch(void* const* d_in, const int* in_sizes, int n_in,
                              void* d_out, int out_size) {
    const float* x         = (const float*)d_in[0];
    const float* ln1_g     = (const float*)d_in[1];
    const float* ln1_b     = (const float*)d_in[2];
    const float* Wq        = (const float*)d_in[3];
    const float* bq        = (const float*)d_in[4];
    const float* Wk        = (const float*)d_in[5];
    const float* bk        = (const float*)d_in[6];
    const float* Wv        = (const float*)d_in[7];
    const float* bv        = (const float*)d_in[8];
    const float* Wo        = (const float*)d_in[9];
    const float* bo        = (const float*)d_in[10];
    const float* time_w    = (const float*)d_in[11];
    const float* time_alpha= (const float*)d_in[12];
    const float* time_beta = (const float*)d_in[13];
    const float* time_gamma= (const float*)d_in[14];
    const float* Wmix      = (const float*)d_in[15];
    const float* ln2_g     = (const float*)d_in[16];
    const float* ln2_b     = (const float*)d_in[17];
    const float* Wgk       = (const float*)d_in[18];
    const float* bgk       = (const float*)d_in[19];
    const float* Wgv       = (const float*)d_in[20];
    const float* bgv       = (const float*)d_in[21];
    const float* Wgw       = (const float*)d_in[22];
    const float* bgw       = (const float*)d_in[23];

    __half *xs, *q, *k, *v, *gvb, *yb, *atth, *xmp;
    float *x1;
    uint32_t* wh;
    cudaGetSymbolAddress((void**)&xs,  g_xs);
    cudaGetSymbolAddress((void**)&q,   g_q);
    cudaGetSymbolAddress((void**)&k,   g_k);
    cudaGetSymbolAddress((void**)&v,   g_v);
    cudaGetSymbolAddress((void**)&yb,  g_y);
    cudaGetSymbolAddress((void**)&x1,  g_x1);
    cudaGetSymbolAddress((void**)&gvb, g_gv);
    cudaGetSymbolAddress((void**)&atth, g_att);
    cudaGetSymbolAddress((void**)&wh,  g_wh);
    cudaGetSymbolAddress((void**)&xmp, g_xm);
    float* part = (float*)atth;

    static bool attr_done = false;
    if (!attr_done) {
        cudaFuncSetAttribute(softmax_mix, cudaFuncAttributeMaxDynamicSharedMemorySize, SMIX_SMEM);
        cudaFuncSetAttribute(gemm_qkv,    cudaFuncAttributeMaxDynamicSharedMemorySize, GEMM_SMEMW * 4);
        cudaFuncSetAttribute(gemm_splitk, cudaFuncAttributeMaxDynamicSharedMemorySize, GEMM_SMEMW * 4);
        cudaFuncSetAttribute(gemm_ffn_dual, cudaFuncAttributeMaxDynamicSharedMemorySize, DUAL_SMEMW * 4);
        attr_done = true;
    }

    const int M = Bn * Tn;   // 2048

    // 0) weight conversion to packed fp16
    W4 w4; w4.w[0] = Wq; w4.w[1] = Wk; w4.w[2] = Wv; w4.w[3] = Wo;
    conv_cc<<<dim3(4, 512, 4), 256>>>(w4);
    conv_cf<<<dim3(16, 512, 2), 256>>>(Wgk, Wgv);
    conv_fc<<<dim3(4, 2048), 256>>>(Wgw);

    // 1) LN1 + time shift
    ln1_shift_kernel<<<Bn * Tn, 256>>>(x, ln1_g, ln1_b);

    // 2) QKV fused; rotary fused; v k-packed
    QKVArgs qa = {bq, bk, bv, q, k, v};
    gemm_qkv<<<dim3(Cn / 128, M / 128, 3), 256, GEMM_SMEMW * 4>>>(xs, qa);

    // 3) scores (triangular grid: 36 causal tile pairs)
    scores_mma<<<dim3(36, Bn * Hn), 256>>>();

    // 4) softmax * w + head mix
    softmax_mix<<<dim3(Tn, Bn), 256, SMIX_SMEM>>>(time_w, time_alpha, time_beta, Wmix);

    // 5) y = att2 @ v
    av_mma<<<dim3(Tn / 128, Bn * Hn), 256>>>();

    // 6) out projection: split-K=2, fused finalize+LN2
    gemm_splitk<<<dim3(Cn / 128, M / 128, 2), 256, GEMM_SMEMW * 4>>>(
        yb, wh + WOFF_O, part, Cn, Cn);
    ln2_fused<<<Bn * Tn, 256>>>(part, bo, time_gamma, x, ln2_g, ln2_b);

    // 7) FFN up: dual GEMM
    gemm_ffn_dual<<<dim3(FFNn / 128, M / 128), 256, DUAL_SMEMW * 4>>>(
        xmp, wh + WOFF_GK, wh + WOFF_GV, bgk, bgv, gvb);

    // 8) FFN down: split-K=2 + finalize
    gemm_splitk<<<dim3(Cn / 128, M / 128, 2), 256, GEMM_SMEMW * 4>>>(
        gvb, wh + WOFF_GW, part, Cn, FFNn);
    fin_wgw<<<(M * Cn) / (256 * 4), 256>>>(part, bgw, x1, (float*)d_out);
}

// round 14
// speedup vs baseline: 1.0567x; 1.0226x over previous
#include <cuda_runtime.h>
#include <cuda_fp16.h>
#include <cstdint>
#include <math.h>

#define Bn   2
#define Tn   1024
#define Cn   1024
#define Hn   16
#define HSn  64
#define TTn  1024
#define FFNn 4096
#define EPSn 1e-6f

// ---------------- scratch ----------------
__device__ __half g_xs [Bn*Tn*Cn];
__device__ __half g_q  [Bn*Tn*Cn];
__device__ __half g_k  [Bn*Tn*Cn];
__device__ __half g_v  [Bn*Tn*Cn];          // k-pair packed per (b,h)
__device__ __half g_att [Bn*Hn*Tn*Tn];      // aliased as fp32 split-K partials
__device__ __half g_att2[Bn*Hn*Tn*Tn];
__device__ __half g_y  [Bn*Tn*Cn];
__device__ float  g_x1 [Bn*Tn*Cn];
__device__ __half g_xm [Bn*Tn*Cn];
__device__ __half g_gv [Bn*Tn*FFNn];
__device__ uint32_t g_wh[8*1024*1024];      // packed half2 weights, 32MB

#define WOFF_Q   0
#define WOFF_K   (512*1024)
#define WOFF_V   (2*512*1024)
#define WOFF_O   (3*512*1024)
#define WOFF_GK  (4*512*1024)
#define WOFF_GV  (WOFF_GK + 512*4096)
#define WOFF_GW  (WOFF_GV + 512*4096)

// ---------------- helpers ----------------
__device__ __forceinline__ void mma_fp16(float* d, const uint32_t* a, const uint32_t* b) {
    asm volatile(
        "mma.sync.aligned.m16n8k16.row.col.f32.f16.f16.f32 "
        "{%0,%1,%2,%3}, {%4,%5,%6,%7}, {%8,%9}, {%0,%1,%2,%3};"
        : "+f"(d[0]), "+f"(d[1]), "+f"(d[2]), "+f"(d[3])
        : "r"(a[0]), "r"(a[1]), "r"(a[2]), "r"(a[3]), "r"(b[0]), "r"(b[1]));
}
__device__ __forceinline__ void ldmat4(uint32_t* r, uint32_t addr) {
    asm volatile(
        "ldmatrix.sync.aligned.m8n8.x4.shared.b16 {%0,%1,%2,%3}, [%4];"
        : "=r"(r[0]), "=r"(r[1]), "=r"(r[2]), "=r"(r[3]) : "r"(addr));
}
__device__ __forceinline__ uint32_t smem_u32(const void* p) {
    uint32_t a;
    asm("{ .reg .u64 t; cvta.to.shared.u64 t, %1; cvt.u32.u64 %0, t; }"
        : "=r"(a) : "l"(p));
    return a;
}
__device__ __forceinline__ void cp16(uint32_t dst, const void* src) {
    asm volatile("cp.async.ca.shared.global [%0], [%1], 16;" :: "r"(dst), "l"(src));
}
__device__ __forceinline__ void cp_commit() {
    asm volatile("cp.async.commit_group;" ::: "memory");
}
template<int N> __device__ __forceinline__ void cp_wait() {
    asm volatile("cp.async.wait_group %0;" :: "n"(N) : "memory");
}

// ---------------- weight conversion ----------------
struct W4 { const float* w[4]; };
__global__ void conv_cc(W4 ws) {
    int z = blockIdx.z;
    const float* W = ws.w[z];
    uint32_t* dst = g_wh + (size_t)z * (512*1024);
    int n  = blockIdx.x * 256 + threadIdx.x;
    int k2 = blockIdx.y;
    __half2 h = __floats2half2_rn(W[(size_t)(2*k2) * Cn + n],
                                  W[(size_t)(2*k2+1) * Cn + n]);
    dst[(size_t)k2 * Cn + n] = *(uint32_t*)&h;
}
__global__ void conv_cf(const float* W0, const float* W1) {
    int z = blockIdx.z;
    const float* W = z ? W1 : W0;
    uint32_t* dst = g_wh + WOFF_GK + (size_t)z * (512*4096);
    int n  = blockIdx.x * 256 + threadIdx.x;
    int k2 = blockIdx.y;
    __half2 h = __floats2half2_rn(W[(size_t)(2*k2) * FFNn + n],
                                  W[(size_t)(2*k2+1) * FFNn + n]);
    dst[(size_t)k2 * FFNn + n] = *(uint32_t*)&h;
}
__global__ void conv_fc(const float* W) {
    uint32_t* dst = g_wh + WOFF_GW;
    int n  = blockIdx.x * 256 + threadIdx.x;
    int k2 = blockIdx.y;
    __half2 h = __floats2half2_rn(W[(size_t)(2*k2) * Cn + n],
                                  W[(size_t)(2*k2+1) * Cn + n]);
    dst[(size_t)k2 * Cn + n] = *(uint32_t*)&h;
}

// ---------------- fast row reduce ----------------
__device__ __forceinline__ void row_stats(float4 v4, float& mean, float& rstd,
                                          float* red) {
    int tid = threadIdx.x, lane = tid & 31, w = tid >> 5;
    float s  = v4.x + v4.y + v4.z + v4.w;
    float s2 = v4.x*v4.x + v4.y*v4.y + v4.z*v4.z + v4.w*v4.w;
#pragma unroll
    for (int o = 16; o; o >>= 1) {
        s  += __shfl_xor_sync(0xFFFFFFFFu, s,  o);
        s2 += __shfl_xor_sync(0xFFFFFFFFu, s2, o);
    }
    if (lane == 0) { red[w] = s; red[8 + w] = s2; }
    __syncthreads();
    if (tid == 0) {
        float a = 0.f, b2 = 0.f;
#pragma unroll
        for (int i = 0; i < 8; i++) { a += red[i]; b2 += red[8 + i]; }
        red[16] = a; red[17] = b2;
    }
    __syncthreads();
    mean = red[16] / Cn;
    rstd = rsqrtf(red[17] / Cn - mean * mean + EPSn);
}

// ---------------- LN1 + time_shift_half ----------------
__global__ __launch_bounds__(256)
void ln1_shift_kernel(const float* __restrict__ x,
                      const float* __restrict__ g,
                      const float* __restrict__ b) {
    __shared__ float red[18];
    int bt = blockIdx.x;
    int bb = bt >> 10, t = bt & (Tn - 1);
    int c = threadIdx.x * 4;
    float4 v4 = *(const float4*)(x + (size_t)bt * Cn + c);
    float mean, rstd;
    row_stats(v4, mean, rstd, red);
    float4 g4 = *(const float4*)(g + c);
    float4 b4 = *(const float4*)(b + c);
    __half2 h01 = __floats2half2_rn((v4.x - mean) * rstd * g4.x + b4.x,
                                    (v4.y - mean) * rstd * g4.y + b4.y);
    __half2 h23 = __floats2half2_rn((v4.z - mean) * rstd * g4.z + b4.z,
                                    (v4.w - mean) * rstd * g4.w + b4.w);
    uint2 pk; pk.x = *(uint32_t*)&h01; pk.y = *(uint32_t*)&h23;
    if (c < Cn / 2) {
        if (t + 1 < Tn)
            *(uint2*)(g_xs + ((size_t)bb * Tn + t + 1) * Cn + c) = pk;
        if (t == 0)
            *(uint2*)(g_xs + (size_t)bb * Tn * Cn + c) = make_uint2(0, 0);
    } else {
        *(uint2*)(g_xs + (size_t)bt * Cn + c) = pk;
    }
}

// ---------------- fused fin_wo + LN2 ----------------
__global__ __launch_bounds__(256)
void ln2_fused(const float* __restrict__ P, const float* __restrict__ bo,
               const float* __restrict__ gamma, const float* __restrict__ x,
               const float* __restrict__ g, const float* __restrict__ b) {
    __shared__ float red[18];
    int bt = blockIdx.x;
    int t = bt & (Tn - 1);
    int c = threadIdx.x * 4;
    const size_t half = (size_t)(Bn * Tn) * Cn;
    size_t i = (size_t)bt * Cn + c;
    float4 a4 = *(const float4*)(P + i);
    float4 p4 = *(const float4*)(P + half + i);
    float4 x4 = *(const float4*)(x + i);
    float4 bo4 = *(const float4*)(bo + c);
    float gm = gamma[t];
    float4 v4;
    v4.x = (a4.x + p4.x + bo4.x) * gm + x4.x;
    v4.y = (a4.y + p4.y + bo4.y) * gm + x4.y;
    v4.z = (a4.z + p4.z + bo4.z) * gm + x4.z;
    v4.w = (a4.w + p4.w + bo4.w) * gm + x4.w;
    *(float4*)(g_x1 + i) = v4;
    float mean, rstd;
    row_stats(v4, mean, rstd, red);
    float4 g4 = *(const float4*)(g + c);
    float4 b4 = *(const float4*)(b + c);
    __half2 h01 = __floats2half2_rn((v4.x - mean) * rstd * g4.x + b4.x,
                                    (v4.y - mean) * rstd * g4.y + b4.y);
    __half2 h23 = __floats2half2_rn((v4.z - mean) * rstd * g4.z + b4.z,
                                    (v4.w - mean) * rstd * g4.w + b4.w);
    uint2 pk; pk.x = *(uint32_t*)&h01; pk.y = *(uint32_t*)&h23;
    *(uint2*)(g_xm + i) = pk;
}

// ================= fp16 GEMM core (128x128, 8 warps, K-chunk 64, 2-stage) ===
#define EPI_NONE  0
#define EPI_QKV   1

#define AW 36
#define BW 136
#define ABUFW (128*AW)
#define BBUFW (32*BW)
#define GEMM_SMEMW (2*(ABUFW+BBUFW))

template<int MODE>
__device__ __forceinline__ void gemm_body(
    uint32_t* usm,
    const __half* __restrict__ A, const uint32_t* __restrict__ Bp,
    const float* __restrict__ bias, void* __restrict__ Cv,
    int N, int Kfull, int koff, int kspan,
    int row0, int col0, int qkvmode)
{
    uint32_t sb = smem_u32(usm);
    int tid = threadIdx.x;
    int lane = tid & 31, wid = tid >> 5;
    int wm = wid >> 2, wn = wid & 3;
    int lg = lane >> 2, lq = lane & 3;

    float acc[4][4][4] = {};

    int aw = (tid & 1) * 16;
    const __half* Ab = A + (size_t)(row0 + (tid >> 1)) * Kfull + koff + aw * 2;
    const uint32_t* Bb = Bp + ((size_t)(koff >> 1) + (tid >> 4)) * N + col0 + (tid & 15) * 8;
    uint32_t adst0 = sb + (uint32_t)(((tid >> 1) * AW + aw) * 4);
    uint32_t bdst0 = sb + (uint32_t)((2 * ABUFW + (tid >> 4) * BW + (tid & 15) * 8) * 4);

    // ldmatrix A lane address: row = wm*64 + (lane&15), k-word offset (lane>>4)*4
    uint32_t albase = sb + (uint32_t)(((wm * 64 + (lane & 15)) * AW + (lane >> 4) * 4) * 4);

    const int nch = kspan >> 6;

#define GISS(ci) do { \
    int _p = (ci) & 1; int _k0 = (ci) << 6; \
    uint32_t _ad = adst0 + _p * ABUFW * 4; \
    const __half* _a = Ab + _k0; \
    cp16(_ad,      _a);      cp16(_ad + 16, _a + 8); \
    cp16(_ad + 32, _a + 16); cp16(_ad + 48, _a + 24); \
    const uint32_t* _bs = Bb + (size_t)(_k0 >> 1) * N; \
    uint32_t _bd = bdst0 + _p * BBUFW * 4; \
    cp16(_bd,      _bs);     cp16(_bd + 16, _bs + 4); \
    cp16(_bd + 16 * BW * 4,      _bs + (size_t)16 * N); \
    cp16(_bd + 16 * BW * 4 + 16, _bs + (size_t)16 * N + 4); \
} while (0)

    GISS(0); cp_commit();

    for (int ci = 0; ci < nch; ci++) {
        cp_wait<0>();
        __syncthreads();
        if (ci + 1 < nch) { GISS(ci + 1); cp_commit(); }

        uint32_t al = albase + (ci & 1) * (ABUFW * 4);
        const uint32_t* uB = usm + 2 * ABUFW + (ci & 1) * BBUFW;
#pragma unroll
        for (int ks = 0; ks < 4; ks++) {
            int kbw = ks * 8;
            uint32_t af[4][4], bf[4][2];
#pragma unroll
            for (int mi = 0; mi < 4; mi++)
                ldmat4(af[mi], al + (uint32_t)((mi * 16 * AW + kbw) * 4));
#pragma unroll
            for (int ni = 0; ni < 4; ni++) {
                int nc = wn * 32 + ni * 8 + lg;
                bf[ni][0] = uB[(kbw + lq) * BW + nc];
                bf[ni][1] = uB[(kbw + 4 + lq) * BW + nc];
            }
#pragma unroll
            for (int mi = 0; mi < 4; mi++)
#pragma unroll
                for (int ni = 0; ni < 4; ni++)
                    mma_fp16(acc[mi][ni], af[mi], bf[ni]);
        }
        __syncthreads();
    }
#undef GISS

    if (MODE == EPI_QKV) {
        __half* out = (__half*)Cv;
#pragma unroll
        for (int mi = 0; mi < 4; mi++) {
#pragma unroll
            for (int hf = 0; hf < 2; hf++) {
                int r = row0 + wm * 64 + mi * 16 + lg + hf * 8;
                int bI = r >> 10, t = r & (Tn - 1);
                float v[4][2];
#pragma unroll
                for (int ni = 0; ni < 4; ni++) {
                    int c = col0 + wn * 32 + ni * 8 + lq * 2;
                    v[ni][0] = acc[mi][ni][hf * 2 + 0] + bias[c];
                    v[ni][1] = acc[mi][ni][hf * 2 + 1] + bias[c + 1];
                }
                if (qkvmode == 0 && !(wn & 1)) {
#pragma unroll
                    for (int ni = 0; ni < 2; ni++) {
                        int d0 = ni * 8 + lq * 2;
#pragma unroll
                        for (int j = 0; j < 2; j++) {
                            float ang = (float)t * exp2f(-0.625f * (float)(d0 + j));
                            float sv, cv;
                            sincosf(ang, &sv, &cv);
                            float a = v[ni][j], b2 = v[ni + 2][j];
                            v[ni][j]     = a * cv - b2 * sv;
                            v[ni + 2][j] = b2 * cv + a * sv;
                        }
                    }
                }
#pragma unroll
                for (int ni = 0; ni < 4; ni++) {
                    int c = col0 + wn * 32 + ni * 8 + lq * 2;
                    int h = c >> 6, d = c & 63;
                    size_t base = ((size_t)bI * Hn + h) * ((size_t)Tn * HSn);
                    __half2 h2 = __floats2half2_rn(v[ni][0], v[ni][1]);
                    if (qkvmode != 2) {
                        *(__half2*)(out + base + (size_t)t * HSn + d) = h2;
                    } else {
                        size_t w = base + ((size_t)(t >> 1) * HSn + d) * 2 + (t & 1);
                        out[w]     = __low2half(h2);
                        out[w + 2] = __high2half(h2);
                    }
                }
            }
        }
    } else {
        float* out = (float*)Cv;
#pragma unroll
        for (int mi = 0; mi < 4; mi++)
#pragma unroll
            for (int ni = 0; ni < 4; ni++)
#pragma unroll
                for (int hf = 0; hf < 2; hf++) {
                    int r = row0 + wm * 64 + mi * 16 + lg + hf * 8;
                    int c = col0 + wn * 32 + ni * 8 + lq * 2;
                    size_t oi = (size_t)r * N + c;
                    out[oi]     = acc[mi][ni][hf * 2 + 0];
                    out[oi + 1] = acc[mi][ni][hf * 2 + 1];
                }
    }
}

struct QKVArgs {
    const float *b0, *b1, *b2;
    __half *q, *k, *v;
};

__global__ __launch_bounds__(256, 2)
void gemm_qkv(const __half* __restrict__ A, QKVArgs a) {
    extern __shared__ uint32_t usm[];
    int z = blockIdx.z;
    const uint32_t* Bp = g_wh + (size_t)z * (512 * 1024);
    const float* bias = (z == 0) ? a.b0 : (z == 1) ? a.b1 : a.b2;
    __half* out = (z == 0) ? a.q : (z == 1) ? a.k : a.v;
    gemm_body<EPI_QKV>(usm, A, Bp, bias, out, Cn, Cn, 0, Cn,
                       blockIdx.y * 128, blockIdx.x * 128, (z == 2) ? 2 : 0);
}

__global__ __launch_bounds__(256, 2)
void gemm_splitk(const __half* __restrict__ A, const uint32_t* __restrict__ Bp,
                 float* __restrict__ P, int N, int Kfull) {
    extern __shared__ uint32_t usm[];
    int z = blockIdx.z;
    int kh = Kfull >> 1;
    float* out = P + (size_t)z * (Bn * Tn) * Cn;
    gemm_body<EPI_NONE>(usm, A, Bp, nullptr, out, N, Kfull, z * kh, kh,
                        blockIdx.y * 128, blockIdx.x * 128, -1);
}

// ================= dual FFN-up GEMM (K-chunk 64, 2-stage) ===================
#define DUAL_SMEMW (2*ABUFW + 4*BBUFW)

__global__ __launch_bounds__(256)
void gemm_ffn_dual(const __half* __restrict__ A,
                   const uint32_t* __restrict__ B1p,
                   const uint32_t* __restrict__ B2p,
                   const float* __restrict__ bias1,
                   const float* __restrict__ bias2,
                   __half* __restrict__ C) {
    extern __shared__ uint32_t usm[];
    const int N = FFNn, K = Cn;
    uint32_t sb = smem_u32(usm);
    int tid = threadIdx.x;
    int lane = tid & 31, wid = tid >> 5;
    int wm = wid >> 2, wn = wid & 3;
    int lg = lane >> 2, lq = lane & 3;
    int row0 = blockIdx.y * 128, col0 = blockIdx.x * 128;

    float acc1[4][4][4] = {};
    float acc2[4][4][4] = {};

    int aw = (tid & 1) * 16;
    const __half* Ab = A + (size_t)(row0 + (tid >> 1)) * K + aw * 2;
    const uint32_t* B1b = B1p + (size_t)(tid >> 4) * N + col0 + (tid & 15) * 8;
    const uint32_t* B2b = B2p + (size_t)(tid >> 4) * N + col0 + (tid & 15) * 8;
    uint32_t adst0 = sb + (uint32_t)(((tid >> 1) * AW + aw) * 4);
    uint32_t b1dst0 = sb + (uint32_t)((2 * ABUFW + (tid >> 4) * BW + (tid & 15) * 8) * 4);
    uint32_t b2dst0 = b1dst0 + 2 * BBUFW * 4;

    uint32_t albase = sb + (uint32_t)(((wm * 64 + (lane & 15)) * AW + (lane >> 4) * 4) * 4);

    const int nch = K >> 6;

#define DISS(ci) do { \
    int _p = (ci) & 1; int _k0 = (ci) << 6; \
    uint32_t _ad = adst0 + _p * ABUFW * 4; \
    const __half* _a = Ab + _k0; \
    cp16(_ad,      _a);      cp16(_ad + 16, _a + 8); \
    cp16(_ad + 32, _a + 16); cp16(_ad + 48, _a + 24); \
    size_t _bo = (size_t)(_k0 >> 1) * N; \
    uint32_t _b1d = b1dst0 + _p * BBUFW * 4; \
    cp16(_b1d,      B1b + _bo);     cp16(_b1d + 16, B1b + _bo + 4); \
    cp16(_b1d + 16 * BW * 4,      B1b + _bo + (size_t)16 * N); \
    cp16(_b1d + 16 * BW * 4 + 16, B1b + _bo + (size_t)16 * N + 4); \
    uint32_t _b2d = b2dst0 + _p * BBUFW * 4; \
    cp16(_b2d,      B2b + _bo);     cp16(_b2d + 16, B2b + _bo + 4); \
    cp16(_b2d + 16 * BW * 4,      B2b + _bo + (size_t)16 * N); \
    cp16(_b2d + 16 * BW * 4 + 16, B2b + _bo + (size_t)16 * N + 4); \
} while (0)

    DISS(0); cp_commit();

    for (int ci = 0; ci < nch; ci++) {
        cp_wait<0>();
        __syncthreads();
        if (ci + 1 < nch) { DISS(ci + 1); cp_commit(); }

        uint32_t al = albase + (ci & 1) * (ABUFW * 4);
        const uint32_t* uB1 = usm + 2 * ABUFW + (ci & 1) * BBUFW;
        const uint32_t* uB2 = uB1 + 2 * BBUFW;
#pragma unroll
        for (int ks = 0; ks < 4; ks++) {
            int kbw = ks * 8;
            uint32_t af[4][4], bf1[4][2], bf2[4][2];
#pragma unroll
            for (int mi = 0; mi < 4; mi++)
                ldmat4(af[mi], al + (uint32_t)((mi * 16 * AW + kbw) * 4));
#pragma unroll
            for (int ni = 0; ni < 4; ni++) {
                int nc = wn * 32 + ni * 8 + lg;
                bf1[ni][0] = uB1[(kbw + lq) * BW + nc];
                bf1[ni][1] = uB1[(kbw + 4 + lq) * BW + nc];
                bf2[ni][0] = uB2[(kbw + lq) * BW + nc];
                bf2[ni][1] = uB2[(kbw + 4 + lq) * BW + nc];
            }
#pragma unroll
            for (int mi = 0; mi < 4; mi++)
#pragma unroll
                for (int ni = 0; ni < 4; ni++) {
                    mma_fp16(acc1[mi][ni], af[mi], bf1[ni]);
                    mma_fp16(acc2[mi][ni], af[mi], bf2[ni]);
                }
        }
        __syncthreads();
    }
#undef DISS

#pragma unroll
    for (int mi = 0; mi < 4; mi++) {
#pragma unroll
        for (int ni = 0; ni < 4; ni++) {
#pragma unroll
            for (int hf = 0; hf < 2; hf++) {
                int r = row0 + wm * 64 + mi * 16 + lg + hf * 8;
                int c = col0 + wn * 32 + ni * 8 + lq * 2;
                float k0 = acc1[mi][ni][hf * 2 + 0] + bias1[c];
                float k1 = acc1[mi][ni][hf * 2 + 1] + bias1[c + 1];
                float m0 = acc2[mi][ni][hf * 2 + 0] + bias2[c];
                float m1 = acc2[mi][ni][hf * 2 + 1] + bias2[c + 1];
                float gl0 = 0.5f * k0 * (1.f + erff(k0 * 0.70710678118654752f));
                float gl1 = 0.5f * k1 * (1.f + erff(k1 * 0.70710678118654752f));
                *(__half2*)(C + (size_t)r * FFNn + c) =
                    __floats2half2_rn(gl0 * m0, gl1 * m1);
            }
        }
    }
}

// finalize Wgw
__global__ void fin_wgw(const float* __restrict__ P, const float* __restrict__ bgw,
                        const float* __restrict__ x1, float* __restrict__ out) {
    size_t i = ((size_t)blockIdx.x * 256 + threadIdx.x) * 4;
    const size_t half = (size_t)(Bn * Tn) * Cn;
    float4 a = *(const float4*)(P + i);
    float4 b = *(const float4*)(P + half + i);
    float4 r = *(const float4*)(x1 + i);
    int c = (int)(i & (Cn - 1));
    float4 o;
    o.x = a.x + b.x + bgw[c]     + r.x;
    o.y = a.y + b.y + bgw[c + 1] + r.y;
    o.z = a.z + b.z + bgw[c + 2] + r.z;
    o.w = a.w + b.w + bgw[c + 3] + r.w;
    *(float4*)(out + i) = o;
}

// ---------------- scores via fp16 mma (NT, triangular grid) ----------------
#define SW 36
__global__ __launch_bounds__(256, 2)
void scores_mma() {
    int i = blockIdx.x;
    int tt = (int)((sqrtf(8.f * (float)i + 1.f) - 1.f) * 0.5f);
    while ((tt + 1) * (tt + 2) / 2 <= i) tt++;
    while (tt * (tt + 1) / 2 > i) tt--;
    int ut = i - tt * (tt + 1) / 2;
    int z = blockIdx.y;
    int row0 = tt * 128, col0 = ut * 128;
    const __half* q = g_q + (size_t)z * Tn * HSn;
    const __half* k = g_k + (size_t)z * Tn * HSn;

    __shared__ uint32_t sq[128 * SW];
    __shared__ uint32_t sk[128 * SW];

    int tid = threadIdx.x;
    int lane = tid & 31, wid = tid >> 5;
    int wm = wid >> 2, wn = wid & 3;
    int lg = lane >> 2, lq = lane & 3;

#pragma unroll
    for (int it = 0; it < 4; it++) {
        int id = it * 256 + tid;
        int row = id >> 3, c8 = id & 7;
        *(uint4*)&sq[row * SW + c8 * 4] =
            *(const uint4*)(q + (size_t)(row0 + row) * HSn + c8 * 8);
        *(uint4*)&sk[row * SW + c8 * 4] =
            *(const uint4*)(k + (size_t)(col0 + row) * HSn + c8 * 8);
    }
    __syncthreads();

    float acc[4][4][4] = {};
#pragma unroll
    for (int ks = 0; ks < 4; ks++) {
        int kbw = ks * 8;
        uint32_t af[4][4], bf[4][2];
#pragma unroll
        for (int mi = 0; mi < 4; mi++) {
            int mr = wm * 64 + mi * 16 + lg;
            af[mi][0] = sq[mr * SW + kbw + lq];
            af[mi][1] = sq[(mr + 8) * SW + kbw + lq];
            af[mi][2] = sq[mr * SW + kbw + 4 + lq];
            af[mi][3] = sq[(mr + 8) * SW + kbw + 4 + lq];
        }
#pragma unroll
        for (int ni = 0; ni < 4; ni++) {
            int nc = wn * 32 + ni * 8 + lg;
            bf[ni][0] = sk[nc * SW + kbw + lq];
            bf[ni][1] = sk[nc * SW + kbw + 4 + lq];
        }
#pragma unroll
        for (int mi = 0; mi < 4; mi++)
#pragma unroll
            for (int ni = 0; ni < 4; ni++)
                mma_fp16(acc[mi][ni], af[mi], bf[ni]);
    }

    __half* out = g_att + (size_t)z * Tn * Tn;
#pragma unroll
    for (int mi = 0; mi < 4; mi++)
#pragma unroll
        for (int ni = 0; ni < 4; ni++)
#pragma unroll
            for (int hf = 0; hf < 2; hf++) {
                int r = row0 + wm * 64 + mi * 16 + lg + hf * 8;
                int c = col0 + wn * 32 + ni * 8 + lq * 2;
                *(__half2*)(out + (size_t)r * Tn + c) =
                    __floats2half2_rn(acc[mi][ni][hf * 2 + 0] * 0.125f,
                                      acc[mi][ni][hf * 2 + 1] * 0.125f);
            }
}

// ---------------- fused softmax (causal) * w + head-mix ----------------
#define SMIX_SMEM ((Hn*Tn + 256) * 4)
__global__ __launch_bounds__(256)
void softmax_mix(const float* __restrict__ time_w,
                 const float* __restrict__ alpha,
                 const float* __restrict__ beta,
                 const float* __restrict__ Wmix) {
    extern __shared__ float sm[];
    float* p  = sm;
    float* wm = sm + Hn * Tn;
    int t = blockIdx.x, b = blockIdx.y;
    int tid = threadIdx.x, lane = tid & 31, w = tid >> 5;
    if (tid < 256) wm[tid] = Wmix[tid];
    int len = t + 1;

#pragma unroll
    for (int hh = 0; hh < 2; hh++) {
        int h = w * 2 + hh;
        const __half* src = g_att + (((size_t)b * Hn + h) * Tn + t) * Tn;
        float* ph = p + h * Tn;
        float mx = -1e30f;
        for (int u = lane; u < len; u += 32) {
            float v = __half2float(src[u]); ph[u] = v; mx = fmaxf(mx, v);
        }
#pragma unroll
        for (int o = 16; o; o >>= 1) mx = fmaxf(mx, __shfl_xor_sync(0xFFFFFFFFu, mx, o));
        float sum = 0.f;
        for (int u = lane; u < len; u += 32) {
            float e = expf(ph[u] - mx); ph[u] = e; sum += e;
        }
#pragma unroll
        for (int o = 16; o; o >>= 1) sum += __shfl_xor_sync(0xFFFFFFFFu, sum, o);
        float inv = 1.f / sum;
        float bt = beta[h * Tn + t];
        const float* twr = time_w + h * TTn + (TTn - 1 - t);
        const float* alr = alpha + h * Tn;
        for (int u = lane; u < len; u += 32)
            ph[u] *= inv * twr[u] * alr[u] * bt;
    }
    __syncthreads();

    int zend = (t / 128) * 128 + 128;
    const size_t stride = (size_t)Tn * Tn;
    for (int u = tid; u < zend; u += 256) {
        size_t obase = (((size_t)b * Hn) * Tn + t) * Tn + u;
        if (u < len) {
            float vals[Hn];
#pragma unroll
            for (int j = 0; j < Hn; j++) vals[j] = p[j * Tn + u];
#pragma unroll
            for (int i = 0; i < Hn; i++) {
                float s = 0.f;
#pragma unroll
                for (int j = 0; j < Hn; j++) s += wm[i * Hn + j] * vals[j];
                g_att2[obase + i * stride] = __float2half(s);
            }
        } else {
#pragma unroll
            for (int i = 0; i < Hn; i++)
                g_att2[obase + i * stride] = __float2half(0.f);
        }
    }
}

// ---------------- y = att2 @ v via fp16 mma ----------------
#define AVW 20
#define VW 72
__global__ __launch_bounds__(256, 2)
void av_mma() {
    __shared__ uint32_t sa2[128 * AVW];
    __shared__ uint32_t sv [16 * VW];
    int tt = blockIdx.x;
    int z  = blockIdx.y;
    int row0 = tt * 128;
    const __half* Am = g_att2 + (size_t)z * Tn * Tn;
    const uint32_t* Vw = (const uint32_t*)g_v + (size_t)z * (Tn * HSn / 2);

    int tid = threadIdx.x;
    int lane = tid & 31, wid = tid >> 5;
    int wm2 = wid >> 1;
    int wn2 = wid & 1;
    int lg = lane >> 2, lq = lane & 3;

    float acc[2][4][4] = {};

    int ar = tid >> 1, ac8 = (tid & 1) * 2;
    int vr = tid >> 4, vc = tid & 15;

    int klim = row0 + 128;
    for (int k0 = 0; k0 < klim; k0 += 32) {
#pragma unroll
        for (int j = 0; j < 2; j++)
            *(uint4*)&sa2[ar * AVW + (ac8 + j) * 4] =
                *(const uint4*)(Am + (size_t)(row0 + ar) * Tn + k0 + (ac8 + j) * 8);
        *(uint4*)&sv[vr * VW + vc * 4] =
            *(const uint4*)(Vw + ((size_t)((k0 >> 1) + vr)) * HSn + vc * 4);
        __syncthreads();
#pragma unroll
        for (int ks = 0; ks < 2; ks++) {
            int kbw = ks * 8;
            uint32_t af[2][4], bf[4][2];
#pragma unroll
            for (int mi = 0; mi < 2; mi++) {
                int mr = wm2 * 32 + mi * 16 + lg;
                af[mi][0] = sa2[mr * AVW + kbw + lq];
                af[mi][1] = sa2[(mr + 8) * AVW + kbw + lq];
                af[mi][2] = sa2[mr * AVW + kbw + 4 + lq];
                af[mi][3] = sa2[(mr + 8) * AVW + kbw + 4 + lq];
            }
#pragma unroll
            for (int ni = 0; ni < 4; ni++) {
                int nc = wn2 * 32 + ni * 8 + lg;
                bf[ni][0] = sv[(kbw + lq) * VW + nc];
                bf[ni][1] = sv[(kbw + 4 + lq) * VW + nc];
            }
#pragma unroll
            for (int mi = 0; mi < 2; mi++)
#pragma unroll
                for (int ni = 0; ni < 4; ni++)
                    mma_fp16(acc[mi][ni], af[mi], bf[ni]);
        }
        __syncthreads();
    }

    int b = z / Hn, h = z % Hn;
#pragma unroll
    for (int mi = 0; mi < 2; mi++)
#pragma unroll
        for (int ni = 0; ni < 4; ni++)
#pragma unroll
            for (int hf = 0; hf < 2; hf++) {
                int t = row0 + wm2 * 32 + mi * 16 + lg + hf * 8;
                int d = wn2 * 32 + ni * 8 + lq * 2;
                size_t oi = ((size_t)b * Tn + t) * Cn + h * HSn + d;
                *(__half2*)(g_y + oi) =
                    __floats2half2_rn(acc[mi][ni][hf * 2 + 0],
                                      acc[mi][ni][hf * 2 + 1]);
            }
}

// ---------------- launch ----------------
extern "C" void kernel_launch(void* const* d_in, const int* in_sizes, int n_in,
                              void* d_out, int out_size) {
    const float* x         = (const float*)d_in[0];
    const float* ln1_g     = (const float*)d_in[1];
    const float* ln1_b     = (const float*)d_in[2];
    const float* Wq        = (const float*)d_in[3];
    const float* bq        = (const float*)d_in[4];
    const float* Wk        = (const float*)d_in[5];
    const float* bk        = (const float*)d_in[6];
    const float* Wv        = (const float*)d_in[7];
    const float* bv        = (const float*)d_in[8];
    const float* Wo        = (const float*)d_in[9];
    const float* bo        = (const float*)d_in[10];
    const float* time_w    = (const float*)d_in[11];
    const float* time_alpha= (const float*)d_in[12];
    const float* time_beta = (const float*)d_in[13];
    const float* time_gamma= (const float*)d_in[14];
    const float* Wmix      = (const float*)d_in[15];
    const float* ln2_g     = (const float*)d_in[16];
    const float* ln2_b     = (const float*)d_in[17];
    const float* Wgk       = (const float*)d_in[18];
    const float* bgk       = (const float*)d_in[19];
    const float* Wgv       = (const float*)d_in[20];
    const float* bgv       = (const float*)d_in[21];
    const float* Wgw       = (const float*)d_in[22];
    const float* bgw       = (const float*)d_in[23];

    __half *xs, *q, *k, *v, *gvb, *yb, *atth, *xmp;
    float *x1;
    uint32_t* wh;
    cudaGetSymbolAddress((void**)&xs,  g_xs);
    cudaGetSymbolAddress((void**)&q,   g_q);
    cudaGetSymbolAddress((void**)&k,   g_k);
    cudaGetSymbolAddress((void**)&v,   g_v);
    cudaGetSymbolAddress((void**)&yb,  g_y);
    cudaGetSymbolAddress((void**)&x1,  g_x1);
    cudaGetSymbolAddress((void**)&gvb, g_gv);
    cudaGetSymbolAddress((void**)&atth, g_att);
    cudaGetSymbolAddress((void**)&wh,  g_wh);
    cudaGetSymbolAddress((void**)&xmp, g_xm);
    float* part = (float*)atth;

    static bool attr_done = false;
    if (!attr_done) {
        cudaFuncSetAttribute(softmax_mix, cudaFuncAttributeMaxDynamicSharedMemorySize, SMIX_SMEM);
        cudaFuncSetAttribute(gemm_qkv,    cudaFuncAttributeMaxDynamicSharedMemorySize, GEMM_SMEMW * 4);
        cudaFuncSetAttribute(gemm_splitk, cudaFuncAttributeMaxDynamicSharedMemorySize, GEMM_SMEMW * 4);
        cudaFuncSetAttribute(gemm_ffn_dual, cudaFuncAttributeMaxDynamicSharedMemorySize, DUAL_SMEMW * 4);
        attr_done = true;
    }

    const int M = Bn * Tn;   // 2048

    // 0) weight conversion to packed fp16
    W4 w4; w4.w[0] = Wq; w4.w[1] = Wk; w4.w[2] = Wv; w4.w[3] = Wo;
    conv_cc<<<dim3(4, 512, 4), 256>>>(w4);
    conv_cf<<<dim3(16, 512, 2), 256>>>(Wgk, Wgv);
    conv_fc<<<dim3(4, 2048), 256>>>(Wgw);

    // 1) LN1 + time shift
    ln1_shift_kernel<<<Bn * Tn, 256>>>(x, ln1_g, ln1_b);

    // 2) QKV fused; rotary fused; v k-packed
    QKVArgs qa = {bq, bk, bv, q, k, v};
    gemm_qkv<<<dim3(Cn / 128, M / 128, 3), 256, GEMM_SMEMW * 4>>>(xs, qa);

    // 3) scores (triangular grid)
    scores_mma<<<dim3(36, Bn * Hn), 256>>>();

    // 4) softmax * w + head mix
    softmax_mix<<<dim3(Tn, Bn), 256, SMIX_SMEM>>>(time_w, time_alpha, time_beta, Wmix);

    // 5) y = att2 @ v
    av_mma<<<dim3(Tn / 128, Bn * Hn), 256>>>();

    // 6) out projection: split-K=2, fused finalize+LN2
    gemm_splitk<<<dim3(Cn / 128, M / 128, 2), 256, GEMM_SMEMW * 4>>>(
        yb, wh + WOFF_O, part, Cn, Cn);
    ln2_fused<<<Bn * Tn, 256>>>(part, bo, time_gamma, x, ln2_g, ln2_b);

    // 7) FFN up: dual GEMM
    gemm_ffn_dual<<<dim3(FFNn / 128, M / 128), 256, DUAL_SMEMW * 4>>>(
        xmp, wh + WOFF_GK, wh + WOFF_GV, bgk, bgv, gvb);

    // 8) FFN down: split-K=2 + finalize
    gemm_splitk<<<dim3(Cn / 128, M / 128, 2), 256, GEMM_SMEMW * 4>>>(
        gvb, wh + WOFF_GW, part, Cn, FFNn);
    fin_wgw<<<(M * Cn) / (256 * 4), 256>>>(part, bgw, x1, (float*)d_out);
}

// round 15
// speedup vs baseline: 1.0666x; 1.0094x over previous
#include <cuda_runtime.h>
#include <cuda_fp16.h>
#include <cstdint>
#include <math.h>

#define Bn   2
#define Tn   1024
#define Cn   1024
#define Hn   16
#define HSn  64
#define TTn  1024
#define FFNn 4096
#define EPSn 1e-6f

// ---------------- scratch ----------------
__device__ __half g_xs [Bn*Tn*Cn];
__device__ __half g_q  [Bn*Tn*Cn];
__device__ __half g_k  [Bn*Tn*Cn];
__device__ __half g_v  [Bn*Tn*Cn];          // k-pair packed per (b,h)
__device__ __half g_att [Bn*Hn*Tn*Tn];      // aliased as fp32 split-K partials
__device__ __half g_att2[Bn*Hn*Tn*Tn];
__device__ __half g_y  [Bn*Tn*Cn];
__device__ float  g_x1 [Bn*Tn*Cn];
__device__ __half g_xm [Bn*Tn*Cn];
__device__ __half g_gv [Bn*Tn*FFNn];
__device__ uint32_t g_wh[8*1024*1024];      // packed half2 weights, 32MB

#define WOFF_Q   0
#define WOFF_K   (512*1024)
#define WOFF_V   (2*512*1024)
#define WOFF_O   (3*512*1024)
#define WOFF_GK  (4*512*1024)
#define WOFF_GV  (WOFF_GK + 512*4096)
#define WOFF_GW  (WOFF_GV + 512*4096)

// ---------------- helpers ----------------
__device__ __forceinline__ void mma_fp16(float* d, const uint32_t* a, const uint32_t* b) {
    asm volatile(
        "mma.sync.aligned.m16n8k16.row.col.f32.f16.f16.f32 "
        "{%0,%1,%2,%3}, {%4,%5,%6,%7}, {%8,%9}, {%0,%1,%2,%3};"
        : "+f"(d[0]), "+f"(d[1]), "+f"(d[2]), "+f"(d[3])
        : "r"(a[0]), "r"(a[1]), "r"(a[2]), "r"(a[3]), "r"(b[0]), "r"(b[1]));
}
__device__ __forceinline__ void ldmat4(uint32_t* r, uint32_t addr) {
    asm volatile(
        "ldmatrix.sync.aligned.m8n8.x4.shared.b16 {%0,%1,%2,%3}, [%4];"
        : "=r"(r[0]), "=r"(r[1]), "=r"(r[2]), "=r"(r[3]) : "r"(addr));
}
__device__ __forceinline__ uint32_t smem_u32(const void* p) {
    uint32_t a;
    asm("{ .reg .u64 t; cvta.to.shared.u64 t, %1; cvt.u32.u64 %0, t; }"
        : "=r"(a) : "l"(p));
    return a;
}
__device__ __forceinline__ void cp16(uint32_t dst, const void* src) {
    asm volatile("cp.async.ca.shared.global [%0], [%1], 16;" :: "r"(dst), "l"(src));
}
__device__ __forceinline__ void cp_commit() {
    asm volatile("cp.async.commit_group;" ::: "memory");
}
template<int N> __device__ __forceinline__ void cp_wait() {
    asm volatile("cp.async.wait_group %0;" :: "n"(N) : "memory");
}

// ---------------- weight conversion ----------------
struct W4 { const float* w[4]; };
__global__ void conv_cc(W4 ws) {
    int z = blockIdx.z;
    const float* W = ws.w[z];
    uint32_t* dst = g_wh + (size_t)z * (512*1024);
    int n  = blockIdx.x * 256 + threadIdx.x;
    int k2 = blockIdx.y;
    __half2 h = __floats2half2_rn(W[(size_t)(2*k2) * Cn + n],
                                  W[(size_t)(2*k2+1) * Cn + n]);
    dst[(size_t)k2 * Cn + n] = *(uint32_t*)&h;
}
__global__ void conv_cf(const float* W0, const float* W1) {
    int z = blockIdx.z;
    const float* W = z ? W1 : W0;
    uint32_t* dst = g_wh + WOFF_GK + (size_t)z * (512*4096);
    int n  = blockIdx.x * 256 + threadIdx.x;
    int k2 = blockIdx.y;
    __half2 h = __floats2half2_rn(W[(size_t)(2*k2) * FFNn + n],
                                  W[(size_t)(2*k2+1) * FFNn + n]);
    dst[(size_t)k2 * FFNn + n] = *(uint32_t*)&h;
}
__global__ void conv_fc(const float* W) {
    uint32_t* dst = g_wh + WOFF_GW;
    int n  = blockIdx.x * 256 + threadIdx.x;
    int k2 = blockIdx.y;
    __half2 h = __floats2half2_rn(W[(size_t)(2*k2) * Cn + n],
                                  W[(size_t)(2*k2+1) * Cn + n]);
    dst[(size_t)k2 * Cn + n] = *(uint32_t*)&h;
}

// ---------------- fast row reduce ----------------
__device__ __forceinline__ void row_stats(float4 v4, float& mean, float& rstd,
                                          float* red) {
    int tid = threadIdx.x, lane = tid & 31, w = tid >> 5;
    float s  = v4.x + v4.y + v4.z + v4.w;
    float s2 = v4.x*v4.x + v4.y*v4.y + v4.z*v4.z + v4.w*v4.w;
#pragma unroll
    for (int o = 16; o; o >>= 1) {
        s  += __shfl_xor_sync(0xFFFFFFFFu, s,  o);
        s2 += __shfl_xor_sync(0xFFFFFFFFu, s2, o);
    }
    if (lane == 0) { red[w] = s; red[8 + w] = s2; }
    __syncthreads();
    if (tid == 0) {
        float a = 0.f, b2 = 0.f;
#pragma unroll
        for (int i = 0; i < 8; i++) { a += red[i]; b2 += red[8 + i]; }
        red[16] = a; red[17] = b2;
    }
    __syncthreads();
    mean = red[16] / Cn;
    rstd = rsqrtf(red[17] / Cn - mean * mean + EPSn);
}

// ---------------- LN1 + time_shift_half ----------------
__global__ __launch_bounds__(256)
void ln1_shift_kernel(const float* __restrict__ x,
                      const float* __restrict__ g,
                      const float* __restrict__ b) {
    __shared__ float red[18];
    int bt = blockIdx.x;
    int bb = bt >> 10, t = bt & (Tn - 1);
    int c = threadIdx.x * 4;
    float4 v4 = *(const float4*)(x + (size_t)bt * Cn + c);
    float mean, rstd;
    row_stats(v4, mean, rstd, red);
    float4 g4 = *(const float4*)(g + c);
    float4 b4 = *(const float4*)(b + c);
    __half2 h01 = __floats2half2_rn((v4.x - mean) * rstd * g4.x + b4.x,
                                    (v4.y - mean) * rstd * g4.y + b4.y);
    __half2 h23 = __floats2half2_rn((v4.z - mean) * rstd * g4.z + b4.z,
                                    (v4.w - mean) * rstd * g4.w + b4.w);
    uint2 pk; pk.x = *(uint32_t*)&h01; pk.y = *(uint32_t*)&h23;
    if (c < Cn / 2) {
        if (t + 1 < Tn)
            *(uint2*)(g_xs + ((size_t)bb * Tn + t + 1) * Cn + c) = pk;
        if (t == 0)
            *(uint2*)(g_xs + (size_t)bb * Tn * Cn + c) = make_uint2(0, 0);
    } else {
        *(uint2*)(g_xs + (size_t)bt * Cn + c) = pk;
    }
}

// ---------------- fused fin_wo + LN2 ----------------
__global__ __launch_bounds__(256)
void ln2_fused(const float* __restrict__ P, const float* __restrict__ bo,
               const float* __restrict__ gamma, const float* __restrict__ x,
               const float* __restrict__ g, const float* __restrict__ b) {
    __shared__ float red[18];
    int bt = blockIdx.x;
    int t = bt & (Tn - 1);
    int c = threadIdx.x * 4;
    const size_t half = (size_t)(Bn * Tn) * Cn;
    size_t i = (size_t)bt * Cn + c;
    float4 a4 = *(const float4*)(P + i);
    float4 p4 = *(const float4*)(P + half + i);
    float4 x4 = *(const float4*)(x + i);
    float4 bo4 = *(const float4*)(bo + c);
    float gm = gamma[t];
    float4 v4;
    v4.x = (a4.x + p4.x + bo4.x) * gm + x4.x;
    v4.y = (a4.y + p4.y + bo4.y) * gm + x4.y;
    v4.z = (a4.z + p4.z + bo4.z) * gm + x4.z;
    v4.w = (a4.w + p4.w + bo4.w) * gm + x4.w;
    *(float4*)(g_x1 + i) = v4;
    float mean, rstd;
    row_stats(v4, mean, rstd, red);
    float4 g4 = *(const float4*)(g + c);
    float4 b4 = *(const float4*)(b + c);
    __half2 h01 = __floats2half2_rn((v4.x - mean) * rstd * g4.x + b4.x,
                                    (v4.y - mean) * rstd * g4.y + b4.y);
    __half2 h23 = __floats2half2_rn((v4.z - mean) * rstd * g4.z + b4.z,
                                    (v4.w - mean) * rstd * g4.w + b4.w);
    uint2 pk; pk.x = *(uint32_t*)&h01; pk.y = *(uint32_t*)&h23;
    *(uint2*)(g_xm + i) = pk;
}

// ================= fp16 GEMM core (128x128, 8 warps, K-chunk 64, 2-stage) ===
#define EPI_NONE  0
#define EPI_QKV   1

#define AW 36
#define BW 136
#define ABUFW (128*AW)
#define BBUFW (32*BW)
#define GEMM_SMEMW (2*(ABUFW+BBUFW))

template<int MODE>
__device__ __forceinline__ void gemm_body(
    uint32_t* usm,
    const __half* __restrict__ A, const uint32_t* __restrict__ Bp,
    const float* __restrict__ bias, void* __restrict__ Cv,
    int N, int Kfull, int koff, int kspan,
    int row0, int col0, int qkvmode)
{
    uint32_t sb = smem_u32(usm);
    int tid = threadIdx.x;
    int lane = tid & 31, wid = tid >> 5;
    int wm = wid >> 2, wn = wid & 3;
    int lg = lane >> 2, lq = lane & 3;

    float acc[4][4][4] = {};

    int aw = (tid & 1) * 16;
    const __half* Ab = A + (size_t)(row0 + (tid >> 1)) * Kfull + koff + aw * 2;
    const uint32_t* Bb = Bp + ((size_t)(koff >> 1) + (tid >> 4)) * N + col0 + (tid & 15) * 8;
    uint32_t adst0 = sb + (uint32_t)(((tid >> 1) * AW + aw) * 4);
    uint32_t bdst0 = sb + (uint32_t)((2 * ABUFW + (tid >> 4) * BW + (tid & 15) * 8) * 4);

    uint32_t albase = sb + (uint32_t)(((wm * 64 + (lane & 15)) * AW + (lane >> 4) * 4) * 4);

    const int nch = kspan >> 6;

#define GISS(ci) do { \
    int _p = (ci) & 1; int _k0 = (ci) << 6; \
    uint32_t _ad = adst0 + _p * ABUFW * 4; \
    const __half* _a = Ab + _k0; \
    cp16(_ad,      _a);      cp16(_ad + 16, _a + 8); \
    cp16(_ad + 32, _a + 16); cp16(_ad + 48, _a + 24); \
    const uint32_t* _bs = Bb + (size_t)(_k0 >> 1) * N; \
    uint32_t _bd = bdst0 + _p * BBUFW * 4; \
    cp16(_bd,      _bs);     cp16(_bd + 16, _bs + 4); \
    cp16(_bd + 16 * BW * 4,      _bs + (size_t)16 * N); \
    cp16(_bd + 16 * BW * 4 + 16, _bs + (size_t)16 * N + 4); \
} while (0)

    GISS(0); cp_commit();

    for (int ci = 0; ci < nch; ci++) {
        cp_wait<0>();
        __syncthreads();
        if (ci + 1 < nch) { GISS(ci + 1); cp_commit(); }

        uint32_t al = albase + (ci & 1) * (ABUFW * 4);
        const uint32_t* uB = usm + 2 * ABUFW + (ci & 1) * BBUFW;
#pragma unroll
        for (int ks = 0; ks < 4; ks++) {
            int kbw = ks * 8;
            uint32_t af[4][4], bf[4][2];
#pragma unroll
            for (int mi = 0; mi < 4; mi++)
                ldmat4(af[mi], al + (uint32_t)((mi * 16 * AW + kbw) * 4));
#pragma unroll
            for (int ni = 0; ni < 4; ni++) {
                int nc = wn * 32 + ni * 8 + lg;
                bf[ni][0] = uB[(kbw + lq) * BW + nc];
                bf[ni][1] = uB[(kbw + 4 + lq) * BW + nc];
            }
#pragma unroll
            for (int mi = 0; mi < 4; mi++)
#pragma unroll
                for (int ni = 0; ni < 4; ni++)
                    mma_fp16(acc[mi][ni], af[mi], bf[ni]);
        }
        __syncthreads();
    }
#undef GISS

    if (MODE == EPI_QKV) {
        __half* out = (__half*)Cv;
#pragma unroll
        for (int mi = 0; mi < 4; mi++) {
#pragma unroll
            for (int hf = 0; hf < 2; hf++) {
                int r = row0 + wm * 64 + mi * 16 + lg + hf * 8;
                int bI = r >> 10, t = r & (Tn - 1);
                float v[4][2];
#pragma unroll
                for (int ni = 0; ni < 4; ni++) {
                    int c = col0 + wn * 32 + ni * 8 + lq * 2;
                    v[ni][0] = acc[mi][ni][hf * 2 + 0] + bias[c];
                    v[ni][1] = acc[mi][ni][hf * 2 + 1] + bias[c + 1];
                }
                if (qkvmode == 0 && !(wn & 1)) {
#pragma unroll
                    for (int ni = 0; ni < 2; ni++) {
                        int d0 = ni * 8 + lq * 2;
#pragma unroll
                        for (int j = 0; j < 2; j++) {
                            float ang = (float)t * exp2f(-0.625f * (float)(d0 + j));
                            float sv, cv;
                            sincosf(ang, &sv, &cv);
                            float a = v[ni][j], b2 = v[ni + 2][j];
                            v[ni][j]     = a * cv - b2 * sv;
                            v[ni + 2][j] = b2 * cv + a * sv;
                        }
                    }
                }
#pragma unroll
                for (int ni = 0; ni < 4; ni++) {
                    int c = col0 + wn * 32 + ni * 8 + lq * 2;
                    int h = c >> 6, d = c & 63;
                    size_t base = ((size_t)bI * Hn + h) * ((size_t)Tn * HSn);
                    __half2 h2 = __floats2half2_rn(v[ni][0], v[ni][1]);
                    if (qkvmode != 2) {
                        *(__half2*)(out + base + (size_t)t * HSn + d) = h2;
                    } else {
                        size_t w = base + ((size_t)(t >> 1) * HSn + d) * 2 + (t & 1);
                        out[w]     = __low2half(h2);
                        out[w + 2] = __high2half(h2);
                    }
                }
            }
        }
    } else {
        float* out = (float*)Cv;
#pragma unroll
        for (int mi = 0; mi < 4; mi++)
#pragma unroll
            for (int ni = 0; ni < 4; ni++)
#pragma unroll
                for (int hf = 0; hf < 2; hf++) {
                    int r = row0 + wm * 64 + mi * 16 + lg + hf * 8;
                    int c = col0 + wn * 32 + ni * 8 + lq * 2;
                    size_t oi = (size_t)r * N + c;
                    out[oi]     = acc[mi][ni][hf * 2 + 0];
                    out[oi + 1] = acc[mi][ni][hf * 2 + 1];
                }
    }
}

struct QKVArgs {
    const float *b0, *b1, *b2;
    __half *q, *k, *v;
};

__global__ __launch_bounds__(256, 2)
void gemm_qkv(const __half* __restrict__ A, QKVArgs a) {
    extern __shared__ uint32_t usm[];
    int z = blockIdx.z;
    const uint32_t* Bp = g_wh + (size_t)z * (512 * 1024);
    const float* bias = (z == 0) ? a.b0 : (z == 1) ? a.b1 : a.b2;
    __half* out = (z == 0) ? a.q : (z == 1) ? a.k : a.v;
    gemm_body<EPI_QKV>(usm, A, Bp, bias, out, Cn, Cn, 0, Cn,
                       blockIdx.y * 128, blockIdx.x * 128, (z == 2) ? 2 : 0);
}

__global__ __launch_bounds__(256, 2)
void gemm_splitk(const __half* __restrict__ A, const uint32_t* __restrict__ Bp,
                 float* __restrict__ P, int N, int Kfull) {
    extern __shared__ uint32_t usm[];
    int z = blockIdx.z;
    int kh = Kfull >> 1;
    float* out = P + (size_t)z * (Bn * Tn) * Cn;
    gemm_body<EPI_NONE>(usm, A, Bp, nullptr, out, N, Kfull, z * kh, kh,
                        blockIdx.y * 128, blockIdx.x * 128, -1);
}

// ================= dual FFN-up GEMM (K-chunk 64, 2-stage) ===================
#define DUAL_SMEMW (2*ABUFW + 4*BBUFW)

__global__ __launch_bounds__(256)
void gemm_ffn_dual(const __half* __restrict__ A,
                   const uint32_t* __restrict__ B1p,
                   const uint32_t* __restrict__ B2p,
                   const float* __restrict__ bias1,
                   const float* __restrict__ bias2,
                   __half* __restrict__ C) {
    extern __shared__ uint32_t usm[];
    const int N = FFNn, K = Cn;
    uint32_t sb = smem_u32(usm);
    int tid = threadIdx.x;
    int lane = tid & 31, wid = tid >> 5;
    int wm = wid >> 2, wn = wid & 3;
    int lg = lane >> 2, lq = lane & 3;
    int row0 = blockIdx.y * 128, col0 = blockIdx.x * 128;

    float acc1[4][4][4] = {};
    float acc2[4][4][4] = {};

    int aw = (tid & 1) * 16;
    const __half* Ab = A + (size_t)(row0 + (tid >> 1)) * K + aw * 2;
    const uint32_t* B1b = B1p + (size_t)(tid >> 4) * N + col0 + (tid & 15) * 8;
    const uint32_t* B2b = B2p + (size_t)(tid >> 4) * N + col0 + (tid & 15) * 8;
    uint32_t adst0 = sb + (uint32_t)(((tid >> 1) * AW + aw) * 4);
    uint32_t b1dst0 = sb + (uint32_t)((2 * ABUFW + (tid >> 4) * BW + (tid & 15) * 8) * 4);
    uint32_t b2dst0 = b1dst0 + 2 * BBUFW * 4;

    uint32_t albase = sb + (uint32_t)(((wm * 64 + (lane & 15)) * AW + (lane >> 4) * 4) * 4);

    const int nch = K >> 6;

#define DISS(ci) do { \
    int _p = (ci) & 1; int _k0 = (ci) << 6; \
    uint32_t _ad = adst0 + _p * ABUFW * 4; \
    const __half* _a = Ab + _k0; \
    cp16(_ad,      _a);      cp16(_ad + 16, _a + 8); \
    cp16(_ad + 32, _a + 16); cp16(_ad + 48, _a + 24); \
    size_t _bo = (size_t)(_k0 >> 1) * N; \
    uint32_t _b1d = b1dst0 + _p * BBUFW * 4; \
    cp16(_b1d,      B1b + _bo);     cp16(_b1d + 16, B1b + _bo + 4); \
    cp16(_b1d + 16 * BW * 4,      B1b + _bo + (size_t)16 * N); \
    cp16(_b1d + 16 * BW * 4 + 16, B1b + _bo + (size_t)16 * N + 4); \
    uint32_t _b2d = b2dst0 + _p * BBUFW * 4; \
    cp16(_b2d,      B2b + _bo);     cp16(_b2d + 16, B2b + _bo + 4); \
    cp16(_b2d + 16 * BW * 4,      B2b + _bo + (size_t)16 * N); \
    cp16(_b2d + 16 * BW * 4 + 16, B2b + _bo + (size_t)16 * N + 4); \
} while (0)

    DISS(0); cp_commit();

    for (int ci = 0; ci < nch; ci++) {
        cp_wait<0>();
        __syncthreads();
        if (ci + 1 < nch) { DISS(ci + 1); cp_commit(); }

        uint32_t al = albase + (ci & 1) * (ABUFW * 4);
        const uint32_t* uB1 = usm + 2 * ABUFW + (ci & 1) * BBUFW;
        const uint32_t* uB2 = uB1 + 2 * BBUFW;
#pragma unroll
        for (int ks = 0; ks < 4; ks++) {
            int kbw = ks * 8;
            uint32_t af[4][4], bf1[4][2], bf2[4][2];
#pragma unroll
            for (int mi = 0; mi < 4; mi++)
                ldmat4(af[mi], al + (uint32_t)((mi * 16 * AW + kbw) * 4));
#pragma unroll
            for (int ni = 0; ni < 4; ni++) {
                int nc = wn * 32 + ni * 8 + lg;
                bf1[ni][0] = uB1[(kbw + lq) * BW + nc];
                bf1[ni][1] = uB1[(kbw + 4 + lq) * BW + nc];
                bf2[ni][0] = uB2[(kbw + lq) * BW + nc];
                bf2[ni][1] = uB2[(kbw + 4 + lq) * BW + nc];
            }
#pragma unroll
            for (int mi = 0; mi < 4; mi++)
#pragma unroll
                for (int ni = 0; ni < 4; ni++) {
                    mma_fp16(acc1[mi][ni], af[mi], bf1[ni]);
                    mma_fp16(acc2[mi][ni], af[mi], bf2[ni]);
                }
        }
        __syncthreads();
    }
#undef DISS

#pragma unroll
    for (int mi = 0; mi < 4; mi++) {
#pragma unroll
        for (int ni = 0; ni < 4; ni++) {
#pragma unroll
            for (int hf = 0; hf < 2; hf++) {
                int r = row0 + wm * 64 + mi * 16 + lg + hf * 8;
                int c = col0 + wn * 32 + ni * 8 + lq * 2;
                float k0 = acc1[mi][ni][hf * 2 + 0] + bias1[c];
                float k1 = acc1[mi][ni][hf * 2 + 1] + bias1[c + 1];
                float m0 = acc2[mi][ni][hf * 2 + 0] + bias2[c];
                float m1 = acc2[mi][ni][hf * 2 + 1] + bias2[c + 1];
                float gl0 = 0.5f * k0 * (1.f + erff(k0 * 0.70710678118654752f));
                float gl1 = 0.5f * k1 * (1.f + erff(k1 * 0.70710678118654752f));
                *(__half2*)(C + (size_t)r * FFNn + c) =
                    __floats2half2_rn(gl0 * m0, gl1 * m1);
            }
        }
    }
}

// finalize Wgw
__global__ void fin_wgw(const float* __restrict__ P, const float* __restrict__ bgw,
                        const float* __restrict__ x1, float* __restrict__ out) {
    size_t i = ((size_t)blockIdx.x * 256 + threadIdx.x) * 4;
    const size_t half = (size_t)(Bn * Tn) * Cn;
    float4 a = *(const float4*)(P + i);
    float4 b = *(const float4*)(P + half + i);
    float4 r = *(const float4*)(x1 + i);
    int c = (int)(i & (Cn - 1));
    float4 o;
    o.x = a.x + b.x + bgw[c]     + r.x;
    o.y = a.y + b.y + bgw[c + 1] + r.y;
    o.z = a.z + b.z + bgw[c + 2] + r.z;
    o.w = a.w + b.w + bgw[c + 3] + r.w;
    *(float4*)(out + i) = o;
}

// ---------------- scores via fp16 mma (NT, triangular grid, ldmatrix) ------
#define SW 36
__global__ __launch_bounds__(256, 2)
void scores_mma() {
    int i = blockIdx.x;
    int tt = (int)((sqrtf(8.f * (float)i + 1.f) - 1.f) * 0.5f);
    while ((tt + 1) * (tt + 2) / 2 <= i) tt++;
    while (tt * (tt + 1) / 2 > i) tt--;
    int ut = i - tt * (tt + 1) / 2;
    int z = blockIdx.y;
    int row0 = tt * 128, col0 = ut * 128;
    const __half* q = g_q + (size_t)z * Tn * HSn;
    const __half* k = g_k + (size_t)z * Tn * HSn;

    __shared__ uint32_t sq[128 * SW];
    __shared__ uint32_t sk[128 * SW];

    int tid = threadIdx.x;
    int lane = tid & 31, wid = tid >> 5;
    int wm = wid >> 2, wn = wid & 3;

#pragma unroll
    for (int it = 0; it < 4; it++) {
        int id = it * 256 + tid;
        int row = id >> 3, c8 = id & 7;
        *(uint4*)&sq[row * SW + c8 * 4] =
            *(const uint4*)(q + (size_t)(row0 + row) * HSn + c8 * 8);
        *(uint4*)&sk[row * SW + c8 * 4] =
            *(const uint4*)(k + (size_t)(col0 + row) * HSn + c8 * 8);
    }
    __syncthreads();

    // ldmatrix lane bases: row = base + (lane&15), word-offset (lane>>4)*4
    uint32_t sqb = smem_u32(sq);
    uint32_t skb = smem_u32(sk);
    uint32_t qal = sqb + (uint32_t)(((wm * 64 + (lane & 15)) * SW + (lane >> 4) * 4) * 4);
    uint32_t kal = skb + (uint32_t)(((wn * 32 + (lane & 15)) * SW + (lane >> 4) * 4) * 4);

    float acc[4][4][4] = {};
#pragma unroll
    for (int ks = 0; ks < 4; ks++) {
        int kbw = ks * 8;
        uint32_t af[4][4], bp[2][4];
#pragma unroll
        for (int mi = 0; mi < 4; mi++)
            ldmat4(af[mi], qal + (uint32_t)((mi * 16 * SW + kbw) * 4));
        // B: x4 covers ni pair (2j, 2j+1): r0=b0[2j], r1=b0[2j+1], r2=b1[2j], r3=b1[2j+1]
#pragma unroll
        for (int j = 0; j < 2; j++)
            ldmat4(bp[j], kal + (uint32_t)((j * 16 * SW + kbw) * 4));
#pragma unroll
        for (int mi = 0; mi < 4; mi++)
#pragma unroll
            for (int ni = 0; ni < 4; ni++) {
                uint32_t bf[2] = { bp[ni >> 1][ni & 1], bp[ni >> 1][2 + (ni & 1)] };
                mma_fp16(acc[mi][ni], af[mi], bf);
            }
    }

    int lg = lane >> 2, lq = lane & 3;
    __half* out = g_att + (size_t)z * Tn * Tn;
#pragma unroll
    for (int mi = 0; mi < 4; mi++)
#pragma unroll
        for (int ni = 0; ni < 4; ni++)
#pragma unroll
            for (int hf = 0; hf < 2; hf++) {
                int r = row0 + wm * 64 + mi * 16 + lg + hf * 8;
                int c = col0 + wn * 32 + ni * 8 + lq * 2;
                *(__half2*)(out + (size_t)r * Tn + c) =
                    __floats2half2_rn(acc[mi][ni][hf * 2 + 0] * 0.125f,
                                      acc[mi][ni][hf * 2 + 1] * 0.125f);
            }
}

// ---------------- fused softmax (causal) * w + head-mix ----------------
#define SMIX_SMEM ((Hn*Tn + 256) * 4)
__global__ __launch_bounds__(256)
void softmax_mix(const float* __restrict__ time_w,
                 const float* __restrict__ alpha,
                 const float* __restrict__ beta,
                 const float* __restrict__ Wmix) {
    extern __shared__ float sm[];
    float* p  = sm;
    float* wm = sm + Hn * Tn;
    int t = blockIdx.x, b = blockIdx.y;
    int tid = threadIdx.x, lane = tid & 31, w = tid >> 5;
    if (tid < 256) wm[tid] = Wmix[tid];
    int len = t + 1;

#pragma unroll
    for (int hh = 0; hh < 2; hh++) {
        int h = w * 2 + hh;
        const __half* src = g_att + (((size_t)b * Hn + h) * Tn + t) * Tn;
        float* ph = p + h * Tn;
        float mx = -1e30f;
        for (int u = lane; u < len; u += 32) {
            float v = __half2float(src[u]); ph[u] = v; mx = fmaxf(mx, v);
        }
#pragma unroll
        for (int o = 16; o; o >>= 1) mx = fmaxf(mx, __shfl_xor_sync(0xFFFFFFFFu, mx, o));
        float sum = 0.f;
        for (int u = lane; u < len; u += 32) {
            float e = expf(ph[u] - mx); ph[u] = e; sum += e;
        }
#pragma unroll
        for (int o = 16; o; o >>= 1) sum += __shfl_xor_sync(0xFFFFFFFFu, sum, o);
        float inv = 1.f / sum;
        float bt = beta[h * Tn + t];
        const float* twr = time_w + h * TTn + (TTn - 1 - t);
        const float* alr = alpha + h * Tn;
        for (int u = lane; u < len; u += 32)
            ph[u] *= inv * twr[u] * alr[u] * bt;
    }
    __syncthreads();

    int zend = (t / 128) * 128 + 128;
    const size_t stride = (size_t)Tn * Tn;
    for (int u = tid; u < zend; u += 256) {
        size_t obase = (((size_t)b * Hn) * Tn + t) * Tn + u;
        if (u < len) {
            float vals[Hn];
#pragma unroll
            for (int j = 0; j < Hn; j++) vals[j] = p[j * Tn + u];
#pragma unroll
            for (int i = 0; i < Hn; i++) {
                float s = 0.f;
#pragma unroll
                for (int j = 0; j < Hn; j++) s += wm[i * Hn + j] * vals[j];
                g_att2[obase + i * stride] = __float2half(s);
            }
        } else {
#pragma unroll
            for (int i = 0; i < Hn; i++)
                g_att2[obase + i * stride] = __float2half(0.f);
        }
    }
}

// ---------------- y = att2 @ v via fp16 mma (ldmatrix A) --------------------
#define AVW 20
#define VW 72
__global__ __launch_bounds__(256, 2)
void av_mma() {
    __shared__ uint32_t sa2[128 * AVW];
    __shared__ uint32_t sv [16 * VW];
    int tt = blockIdx.x;
    int z  = blockIdx.y;
    int row0 = tt * 128;
    const __half* Am = g_att2 + (size_t)z * Tn * Tn;
    const uint32_t* Vw = (const uint32_t*)g_v + (size_t)z * (Tn * HSn / 2);

    int tid = threadIdx.x;
    int lane = tid & 31, wid = tid >> 5;
    int wm2 = wid >> 1;
    int wn2 = wid & 1;
    int lg = lane >> 2, lq = lane & 3;

    float acc[2][4][4] = {};

    int ar = tid >> 1, ac8 = (tid & 1) * 2;
    int vr = tid >> 4, vc = tid & 15;

    uint32_t sa2b = smem_u32(sa2);
    uint32_t aal = sa2b + (uint32_t)(((wm2 * 32 + (lane & 15)) * AVW + (lane >> 4) * 4) * 4);

    int klim = row0 + 128;
    for (int k0 = 0; k0 < klim; k0 += 32) {
#pragma unroll
        for (int j = 0; j < 2; j++)
            *(uint4*)&sa2[ar * AVW + (ac8 + j) * 4] =
                *(const uint4*)(Am + (size_t)(row0 + ar) * Tn + k0 + (ac8 + j) * 8);
        *(uint4*)&sv[vr * VW + vc * 4] =
            *(const uint4*)(Vw + ((size_t)((k0 >> 1) + vr)) * HSn + vc * 4);
        __syncthreads();
#pragma unroll
        for (int ks = 0; ks < 2; ks++) {
            int kbw = ks * 8;
            uint32_t af[2][4], bf[4][2];
#pragma unroll
            for (int mi = 0; mi < 2; mi++)
                ldmat4(af[mi], aal + (uint32_t)((mi * 16 * AVW + kbw) * 4));
#pragma unroll
            for (int ni = 0; ni < 4; ni++) {
                int nc = wn2 * 32 + ni * 8 + lg;
                bf[ni][0] = sv[(kbw + lq) * VW + nc];
                bf[ni][1] = sv[(kbw + 4 + lq) * VW + nc];
            }
#pragma unroll
            for (int mi = 0; mi < 2; mi++)
#pragma unroll
                for (int ni = 0; ni < 4; ni++)
                    mma_fp16(acc[mi][ni], af[mi], bf[ni]);
        }
        __syncthreads();
    }

    int b = z / Hn, h = z % Hn;
#pragma unroll
    for (int mi = 0; mi < 2; mi++)
#pragma unroll
        for (int ni = 0; ni < 4; ni++)
#pragma unroll
            for (int hf = 0; hf < 2; hf++) {
                int t = row0 + wm2 * 32 + mi * 16 + lg + hf * 8;
                int d = wn2 * 32 + ni * 8 + lq * 2;
                size_t oi = ((size_t)b * Tn + t) * Cn + h * HSn + d;
                *(__half2*)(g_y + oi) =
                    __floats2half2_rn(acc[mi][ni][hf * 2 + 0],
                                      acc[mi][ni][hf * 2 + 1]);
            }
}

// ---------------- launch ----------------
extern "C" void kernel_launch(void* const* d_in, const int* in_sizes, int n_in,
                              void* d_out, int out_size) {
    const float* x         = (const float*)d_in[0];
    const float* ln1_g     = (const float*)d_in[1];
    const float* ln1_b     = (const float*)d_in[2];
    const float* Wq        = (const float*)d_in[3];
    const float* bq        = (const float*)d_in[4];
    const float* Wk        = (const float*)d_in[5];
    const float* bk        = (const float*)d_in[6];
    const float* Wv        = (const float*)d_in[7];
    const float* bv        = (const float*)d_in[8];
    const float* Wo        = (const float*)d_in[9];
    const float* bo        = (const float*)d_in[10];
    const float* time_w    = (const float*)d_in[11];
    const float* time_alpha= (const float*)d_in[12];
    const float* time_beta = (const float*)d_in[13];
    const float* time_gamma= (const float*)d_in[14];
    const float* Wmix      = (const float*)d_in[15];
    const float* ln2_g     = (const float*)d_in[16];
    const float* ln2_b     = (const float*)d_in[17];
    const float* Wgk       = (const float*)d_in[18];
    const float* bgk       = (const float*)d_in[19];
    const float* Wgv       = (const float*)d_in[20];
    const float* bgv       = (const float*)d_in[21];
    const float* Wgw       = (const float*)d_in[22];
    const float* bgw       = (const float*)d_in[23];

    __half *xs, *q, *k, *v, *gvb, *yb, *atth, *xmp;
    float *x1;
    uint32_t* wh;
    cudaGetSymbolAddress((void**)&xs,  g_xs);
    cudaGetSymbolAddress((void**)&q,   g_q);
    cudaGetSymbolAddress((void**)&k,   g_k);
    cudaGetSymbolAddress((void**)&v,   g_v);
    cudaGetSymbolAddress((void**)&yb,  g_y);
    cudaGetSymbolAddress((void**)&x1,  g_x1);
    cudaGetSymbolAddress((void**)&gvb, g_gv);
    cudaGetSymbolAddress((void**)&atth, g_att);
    cudaGetSymbolAddress((void**)&wh,  g_wh);
    cudaGetSymbolAddress((void**)&xmp, g_xm);
    float* part = (float*)atth;

    static bool attr_done = false;
    if (!attr_done) {
        cudaFuncSetAttribute(softmax_mix, cudaFuncAttributeMaxDynamicSharedMemorySize, SMIX_SMEM);
        cudaFuncSetAttribute(gemm_qkv,    cudaFuncAttributeMaxDynamicSharedMemorySize, GEMM_SMEMW * 4);
        cudaFuncSetAttribute(gemm_splitk, cudaFuncAttributeMaxDynamicSharedMemorySize, GEMM_SMEMW * 4);
        cudaFuncSetAttribute(gemm_ffn_dual, cudaFuncAttributeMaxDynamicSharedMemorySize, DUAL_SMEMW * 4);
        attr_done = true;
    }

    const int M = Bn * Tn;   // 2048

    // 0) weight conversion to packed fp16
    W4 w4; w4.w[0] = Wq; w4.w[1] = Wk; w4.w[2] = Wv; w4.w[3] = Wo;
    conv_cc<<<dim3(4, 512, 4), 256>>>(w4);
    conv_cf<<<dim3(16, 512, 2), 256>>>(Wgk, Wgv);
    conv_fc<<<dim3(4, 2048), 256>>>(Wgw);

    // 1) LN1 + time shift
    ln1_shift_kernel<<<Bn * Tn, 256>>>(x, ln1_g, ln1_b);

    // 2) QKV fused; rotary fused; v k-packed
    QKVArgs qa = {bq, bk, bv, q, k, v};
    gemm_qkv<<<dim3(Cn / 128, M / 128, 3), 256, GEMM_SMEMW * 4>>>(xs, qa);

    // 3) scores (triangular grid)
    scores_mma<<<dim3(36, Bn * Hn), 256>>>();

    // 4) softmax * w + head mix
    softmax_mix<<<dim3(Tn, Bn), 256, SMIX_SMEM>>>(time_w, time_alpha, time_beta, Wmix);

    // 5) y = att2 @ v
    av_mma<<<dim3(Tn / 128, Bn * Hn), 256>>>();

    // 6) out projection: split-K=2, fused finalize+LN2
    gemm_splitk<<<dim3(Cn / 128, M / 128, 2), 256, GEMM_SMEMW * 4>>>(
        yb, wh + WOFF_O, part, Cn, Cn);
    ln2_fused<<<Bn * Tn, 256>>>(part, bo, time_gamma, x, ln2_g, ln2_b);

    // 7) FFN up: dual GEMM
    gemm_ffn_dual<<<dim3(FFNn / 128, M / 128), 256, DUAL_SMEMW * 4>>>(
        xmp, wh + WOFF_GK, wh + WOFF_GV, bgk, bgv, gvb);

    // 8) FFN down: split-K=2 + finalize
    gemm_splitk<<<dim3(Cn / 128, M / 128, 2), 256, GEMM_SMEMW * 4>>>(
        gvb, wh + WOFF_GW, part, Cn, FFNn);
    fin_wgw<<<(M * Cn) / (256 * 4), 256>>>(part, bgw, x1, (float*)d_out);
}